// round 12
// baseline (speedup 1.0000x reference)
#include <cuda_runtime.h>
#include <cstdint>

// Problem constants.
#define T_SEQ   4096
#define D_MODEL 2048
#define N_HEADS 32
#define D_HEAD  64
#define BATCH   2
#define M_ROWS  (BATCH * T_SEQ)   // 8192
#define NBLK    (T_SEQ / 128)     // 32

// Scratch (device globals: allocation-free rule).
__device__ float g_Q [M_ROWS * D_MODEL];
__device__ float g_K [M_ROWS * D_MODEL];
__device__ float g_V [M_ROWS * D_MODEL];
__device__ float g_A [M_ROWS * D_MODEL];
__device__ float g_Xr[M_ROWS * D_MODEL];
__device__ float g_Wq[D_MODEL * D_MODEL];
__device__ float g_Wk[D_MODEL * D_MODEL];
__device__ float g_Wv[D_MODEL * D_MODEL];
__device__ float g_Wo[D_MODEL * D_MODEL];

// ---------------------------------------------------------------------------
// Helpers
// ---------------------------------------------------------------------------
__device__ __forceinline__ uint32_t smem_u32(const void* p) {
    uint32_t a;
    asm("{ .reg .u64 t; cvta.to.shared.u64 t, %1; cvt.u32.u64 %0, t; }" : "=r"(a) : "l"(p));
    return a;
}
__device__ __forceinline__ void cp16(uint32_t s, const void* g) {
    asm volatile("cp.async.cg.shared.global [%0], [%1], 16;" :: "r"(s), "l"(g));
}
__device__ __forceinline__ float to_tf32(float x) {
    uint32_t u;
    asm("cvt.rna.tf32.f32 %0, %1;" : "=r"(u) : "f"(x));
    return __uint_as_float(u);
}
#define SW128(b) ((b) ^ (((b) >> 3) & 0x70))

__device__ __forceinline__ void ldsm4(uint32_t& a, uint32_t& b, uint32_t& c,
                                      uint32_t& d, uint32_t addr) {
    asm volatile("ldmatrix.sync.aligned.m8n8.x4.shared.b16 {%0,%1,%2,%3}, [%4];"
                 : "=r"(a), "=r"(b), "=r"(c), "=r"(d) : "r"(addr));
}
__device__ __forceinline__ void mma8(float* c, const uint32_t* a, const uint32_t* b) {
    asm volatile("mma.sync.aligned.m16n8k8.row.col.f32.tf32.tf32.f32 "
                 "{%0,%1,%2,%3},{%4,%5,%6,%7},{%8,%9},{%0,%1,%2,%3};"
                 : "+f"(c[0]), "+f"(c[1]), "+f"(c[2]), "+f"(c[3])
                 : "r"(a[0]), "r"(a[1]), "r"(a[2]), "r"(a[3]),
                   "r"(b[0]), "r"(b[1]));
}

// ---------------------------------------------------------------------------
// tf32 rounding prep
// ---------------------------------------------------------------------------
__global__ void round_tf32_kernel(const float4* __restrict__ src,
                                  float4* __restrict__ dst, int n4) {
    int i = blockIdx.x * blockDim.x + threadIdx.x;
    if (i < n4) {
        float4 v = src[i];
        v.x = to_tf32(v.x); v.y = to_tf32(v.y);
        v.z = to_tf32(v.z); v.w = to_tf32(v.w);
        dst[i] = v;
    }
}

// ---------------------------------------------------------------------------
// C[m,n] = sum_k A[m,k]*B[n,k]  (A MxK, B NxK row-major, tf32-prerounded).
// Tile 256x128, BK=32, 8 warps (4x2), warp tile 64x64, 3-stage cp.async.
// MMA:LDSM = 32:8 per k-step (vs 16:6 in the 128x128 version).
// ---------------------------------------------------------------------------
#define BK 32
#define A_STAGE 32768                  // 256 rows * 128B
#define B_STAGE 16384                  // 128 rows * 128B
#define STAGE_BYTES (A_STAGE + B_STAGE)       // 49152
#define GEMM_SMEM (3 * STAGE_BYTES)           // 147456

__device__ __forceinline__ void gemm_load_chunk(uint32_t smb, int kc,
                                                const float* ag, const float* bg,
                                                uint32_t soff) {
    uint32_t ab = smb + (uint32_t)(kc % 3) * STAGE_BYTES;
    uint32_t bb = ab + A_STAGE;
    const float* agp = ag + kc * BK;
    const float* bgp = bg + kc * BK;
#pragma unroll
    for (int i = 0; i < 8; i++)
        cp16(ab + soff + i * 4096, agp + (size_t)i * 32 * D_MODEL);
#pragma unroll
    for (int i = 0; i < 4; i++)
        cp16(bb + soff + i * 4096, bgp + (size_t)i * 32 * D_MODEL);
    asm volatile("cp.async.commit_group;" ::: "memory");
}

__global__ __launch_bounds__(256, 1) void gemm_tf32(const float* __restrict__ A,
                                                    const float* __restrict__ B,
                                                    float* __restrict__ C) {
    extern __shared__ __align__(1024) char sm[];
    uint32_t smb = smem_u32(sm);
    const int tid = threadIdx.x;
    const int wid = tid >> 5, lane = tid & 31;
    const int wm = wid & 3;        // warp M index (0..3), 64 rows each
    const int wn = wid >> 2;       // warp N index (0..1), 64 cols each
    const int bm = blockIdx.y * 256, bn = blockIdx.x * 128;

    // Loader: 8 A rows + 4 B rows (one float4 each) per chunk.
    const int r0 = tid >> 3;       // 0..31
    const int c4 = tid & 7;        // float4 col
    const float* ag = A + (size_t)(bm + r0) * D_MODEL + c4 * 4;
    const float* bg = B + (size_t)(bn + r0) * D_MODEL + c4 * 4;
    const uint32_t soff = SW128((uint32_t)(r0 * 128 + c4 * 16));

    const int lg = lane >> 3, lr = lane & 7;
    const int a_row = (lg & 1) * 8 + lr;
    const int a_k16 = (lg >> 1) * 16;
    const int b_row = (lg >> 1) * 8 + lr;
    const int b_k16 = (lg & 1) * 16;

    float  Cacc[4][8][4];
    uint32_t Af[4][4], Bf[8][2];
#pragma unroll
    for (int i = 0; i < 4; i++)
#pragma unroll
        for (int j = 0; j < 8; j++)
#pragma unroll
            for (int q = 0; q < 4; q++) Cacc[i][j][q] = 0.f;

    gemm_load_chunk(smb, 0, ag, bg, soff);
    gemm_load_chunk(smb, 1, ag, bg, soff);

    const int NCHUNK = D_MODEL / BK;  // 64
    for (int c = 0; c < NCHUNK; c++) {
        if (c == NCHUNK - 1)
            asm volatile("cp.async.wait_group 0;" ::: "memory");
        else
            asm volatile("cp.async.wait_group 1;" ::: "memory");
        __syncthreads();
        if (c + 2 < NCHUNK) gemm_load_chunk(smb, c + 2, ag, bg, soff);

        uint32_t sa = smb + (uint32_t)(c % 3) * STAGE_BYTES;
        uint32_t sb = sa + A_STAGE;
#pragma unroll
        for (int ks = 0; ks < 4; ks++) {
            const int kb = ks * 32;
#pragma unroll
            for (int ma = 0; ma < 4; ma++) {
                int row = wm * 64 + ma * 16 + a_row;
                uint32_t off = (uint32_t)(row * 128 + ((row & 7) * 16 ^ (kb + a_k16)));
                ldsm4(Af[ma][0], Af[ma][1], Af[ma][2], Af[ma][3], sa + off);
            }
#pragma unroll
            for (int p = 0; p < 4; p++) {
                int n = wn * 64 + p * 16 + b_row;
                uint32_t off = (uint32_t)(n * 128 + ((n & 7) * 16 ^ (kb + b_k16)));
                ldsm4(Bf[p * 2][0], Bf[p * 2][1], Bf[p * 2 + 1][0], Bf[p * 2 + 1][1],
                      sb + off);
            }
#pragma unroll
            for (int ma = 0; ma < 4; ma++)
#pragma unroll
                for (int na = 0; na < 8; na++)
                    mma8(Cacc[ma][na], Af[ma], Bf[na]);
        }
        // No trailing __syncthreads(): next iteration's top sync orders reuse.
    }

    const int er = lane >> 2, ec = (lane & 3) * 2;
#pragma unroll
    for (int ma = 0; ma < 4; ma++) {
        int grow = bm + wm * 64 + ma * 16 + er;
#pragma unroll
        for (int na = 0; na < 8; na++) {
            int gcol = bn + wn * 64 + na * 8 + ec;
            float* cp0 = C + (size_t)grow * D_MODEL + gcol;
            float* cp1 = C + (size_t)(grow + 8) * D_MODEL + gcol;
            *(float2*)cp0 = make_float2(Cacc[ma][na][0], Cacc[ma][na][1]);
            *(float2*)cp1 = make_float2(Cacc[ma][na][2], Cacc[ma][na][3]);
        }
    }
}

// ---------------------------------------------------------------------------
// Tensor-core fused sliding-window attention (unchanged from round 9).
// ---------------------------------------------------------------------------
#define AT_Q 0
#define AT_K 32768
#define AT_V 98304
#define AT_SMEM 163840

__global__ __launch_bounds__(256, 1) void swa_attn_tc(const float* __restrict__ Q,
                                                      const float* __restrict__ Kmat,
                                                      const float* __restrict__ V,
                                                      float* __restrict__ O) {
    extern __shared__ __align__(1024) char sm[];
    uint32_t smb = smem_u32(sm);
    float* smf = (float*)sm;

    const int tid  = threadIdx.x;
    const int wid  = tid >> 5, lane = tid & 31;
    const int iblk = blockIdx.x;
    const int h    = blockIdx.y;
    const int b    = blockIdx.z;
    const int row0 = b * T_SEQ + iblk * 128;
    const int colh = h * D_HEAD;
    const int bbase = b * T_SEQ;

    for (int idx = tid; idx < 128 * 16; idx += 256) {
        int r = idx >> 4, d4 = idx & 15;
        int panel = d4 >> 3, x = (d4 & 7) * 16;
        cp16(smb + AT_Q + panel * 16384 + r * 128 + (x ^ ((r & 7) * 16)),
             Q + (size_t)(row0 + r) * D_MODEL + colh + d4 * 4);
    }
    asm volatile("cp.async.commit_group;" ::: "memory");

    {
        int krow = row0 - 128 + tid;
        if (krow < bbase) krow = bbase;
        const float* kg = Kmat + (size_t)krow * D_MODEL + colh;
        uint32_t kbase = smb + AT_K + tid * 128;
#pragma unroll
        for (int d4 = 0; d4 < 16; d4++) {
            float4 v = *(const float4*)(kg + d4 * 4);
            v.x = to_tf32(v.x); v.y = to_tf32(v.y);
            v.z = to_tf32(v.z); v.w = to_tf32(v.w);
            int panel = d4 >> 3, x = (d4 & 7) * 16;
            *(float4*)(sm + (kbase - smb) + panel * 32768 + (x ^ ((tid & 7) * 16))) = v;
        }
    }
    {
        int krow = row0 - 128 + tid;
        if (krow < bbase) krow = bbase;
        const float* vg = V + (size_t)krow * D_MODEL + colh;
        const int kp = tid >> 5;
        const int kx = (tid & 31) * 4;
        const int vbase = (AT_V >> 2) + kp * 2048;
#pragma unroll
        for (int d4 = 0; d4 < 16; d4++) {
            float4 v = *(const float4*)(vg + d4 * 4);
            int d = d4 * 4;
            smf[vbase + (d + 0) * 32 + (((uint32_t)kx ^ (((d + 0) & 7) * 16)) >> 2)] = to_tf32(v.x);
            smf[vbase + (d + 1) * 32 + (((uint32_t)kx ^ (((d + 1) & 7) * 16)) >> 2)] = to_tf32(v.y);
            smf[vbase + (d + 2) * 32 + (((uint32_t)kx ^ (((d + 2) & 7) * 16)) >> 2)] = to_tf32(v.z);
            smf[vbase + (d + 3) * 32 + (((uint32_t)kx ^ (((d + 3) & 7) * 16)) >> 2)] = to_tf32(v.w);
        }
    }
    asm volatile("cp.async.wait_group 0;" ::: "memory");
    __syncthreads();

    const int lg = lane >> 3, lr = lane & 7;
    const int a_row = (lg & 1) * 8 + lr;
    const int a_k16 = (lg >> 1) * 16;
    const int b_row = (lg >> 1) * 8 + lr;
    const int b_k16 = (lg & 1) * 16;
    const int q4 = lane & 3;

    float P[32][4];
#pragma unroll
    for (int i = 0; i < 32; i++)
#pragma unroll
        for (int j = 0; j < 4; j++) P[i][j] = 0.f;

    {
        const int arow_g = wid * 16 + a_row;
        uint32_t Ar[4], Ahi[4], Alo[4], B0, B1, B2, B3;
#pragma unroll
        for (int ks = 0; ks < 8; ks++) {
            int kbyte = ks * 32 + a_k16;
            ldsm4(Ar[0], Ar[1], Ar[2], Ar[3],
                  smb + AT_Q + (kbyte >> 7) * 16384 + arow_g * 128 +
                  ((kbyte & 127) ^ ((arow_g & 7) * 16)));
#pragma unroll
            for (int i = 0; i < 4; i++) {
                float x = __uint_as_float(Ar[i]);
                float hi = to_tf32(x);
                Ahi[i] = __float_as_uint(hi);
                Alo[i] = __float_as_uint(to_tf32(x - hi));
            }
            int kbb = ks * 32 + b_k16;
            uint32_t pb = smb + AT_K + (kbb >> 7) * 32768;
            int xb = kbb & 127;
#pragma unroll
            for (int np = 0; np < 16; np++) {
                int c = np * 16 + b_row;
                ldsm4(B0, B1, B2, B3, pb + c * 128 + (xb ^ ((c & 7) * 16)));
                uint32_t bf0[2] = {B0, B1}, bf1[2] = {B2, B3};
                mma8(P[2 * np], Ahi, bf0);
                mma8(P[2 * np], Alo, bf0);
                mma8(P[2 * np + 1], Ahi, bf1);
                mma8(P[2 * np + 1], Alo, bf1);
            }
        }
    }

    const int r_lo = wid * 16 + (lane >> 2);
    const int r_hi = r_lo + 8;
    const float scale = 0.125f;
    float m_lo = -1e30f, m_hi = -1e30f;
#pragma unroll
    for (int na = 0; na < 32; na++) {
        int c0 = 8 * na + 2 * q4, c1 = c0 + 1;
        bool ok0 = (iblk > 0 || c0 >= 128);
        bool ok1 = (iblk > 0 || c1 >= 128);
        float s0 = (ok0 && c0 >= r_lo && c0 <= r_lo + 128) ? P[na][0] * scale : -1e30f;
        float s1 = (ok1 && c1 >= r_lo && c1 <= r_lo + 128) ? P[na][1] * scale : -1e30f;
        float s2 = (ok0 && c0 >= r_hi && c0 <= r_hi + 128) ? P[na][2] * scale : -1e30f;
        float s3 = (ok1 && c1 >= r_hi && c1 <= r_hi + 128) ? P[na][3] * scale : -1e30f;
        P[na][0] = s0; P[na][1] = s1; P[na][2] = s2; P[na][3] = s3;
        m_lo = fmaxf(m_lo, fmaxf(s0, s1));
        m_hi = fmaxf(m_hi, fmaxf(s2, s3));
    }
    m_lo = fmaxf(m_lo, __shfl_xor_sync(0xffffffff, m_lo, 1));
    m_lo = fmaxf(m_lo, __shfl_xor_sync(0xffffffff, m_lo, 2));
    m_hi = fmaxf(m_hi, __shfl_xor_sync(0xffffffff, m_hi, 1));
    m_hi = fmaxf(m_hi, __shfl_xor_sync(0xffffffff, m_hi, 2));
    float s_lo = 0.f, s_hi = 0.f;
#pragma unroll
    for (int na = 0; na < 32; na++) {
        float e0 = __expf(P[na][0] - m_lo);
        float e1 = __expf(P[na][1] - m_lo);
        float e2 = __expf(P[na][2] - m_hi);
        float e3 = __expf(P[na][3] - m_hi);
        P[na][0] = e0; P[na][1] = e1; P[na][2] = e2; P[na][3] = e3;
        s_lo += e0 + e1; s_hi += e2 + e3;
    }
    s_lo += __shfl_xor_sync(0xffffffff, s_lo, 1);
    s_lo += __shfl_xor_sync(0xffffffff, s_lo, 2);
    s_hi += __shfl_xor_sync(0xffffffff, s_hi, 1);
    s_hi += __shfl_xor_sync(0xffffffff, s_hi, 2);
    const float inv_lo = 1.f / s_lo, inv_hi = 1.f / s_hi;

    float O8[8][4];
#pragma unroll
    for (int i = 0; i < 8; i++)
#pragma unroll
        for (int j = 0; j < 4; j++) O8[i][j] = 0.f;

    const int src1 = (lane & ~3) | (q4 >> 1);
    const int src2 = src1 + 2;
#pragma unroll
    for (int ks = 0; ks < 32; ks++) {
        float u, v, a0f, a1f, a2f, a3f;
        u = __shfl_sync(0xffffffff, P[ks][0], src1);
        v = __shfl_sync(0xffffffff, P[ks][1], src1);
        a0f = (q4 & 1) ? v : u;
        u = __shfl_sync(0xffffffff, P[ks][2], src1);
        v = __shfl_sync(0xffffffff, P[ks][3], src1);
        a1f = (q4 & 1) ? v : u;
        u = __shfl_sync(0xffffffff, P[ks][0], src2);
        v = __shfl_sync(0xffffffff, P[ks][1], src2);
        a2f = (q4 & 1) ? v : u;
        u = __shfl_sync(0xffffffff, P[ks][2], src2);
        v = __shfl_sync(0xffffffff, P[ks][3], src2);
        a3f = (q4 & 1) ? v : u;
        uint32_t Au[4] = {__float_as_uint(to_tf32(a0f)), __float_as_uint(to_tf32(a1f)),
                          __float_as_uint(to_tf32(a2f)), __float_as_uint(to_tf32(a3f))};
        uint32_t vp = smb + AT_V + (ks >> 2) * 8192;
        int kb2 = (ks & 3) * 32 + b_k16;
        uint32_t B0, B1, B2, B3;
#pragma unroll
        for (int p = 0; p < 4; p++) {
            int d = p * 16 + b_row;
            ldsm4(B0, B1, B2, B3, vp + d * 128 + (kb2 ^ ((d & 7) * 16)));
            uint32_t bf0[2] = {B0, B1}, bf1[2] = {B2, B3};
            mma8(O8[2 * p], Au, bf0);
            mma8(O8[2 * p + 1], Au, bf1);
        }
    }

#pragma unroll
    for (int na = 0; na < 8; na++) {
        int gcol = colh + 8 * na + 2 * q4;
        float* o0 = O + (size_t)(row0 + r_lo) * D_MODEL + gcol;
        float* o1 = O + (size_t)(row0 + r_hi) * D_MODEL + gcol;
        *(float2*)o0 = make_float2(to_tf32(O8[na][0] * inv_lo), to_tf32(O8[na][1] * inv_lo));
        *(float2*)o1 = make_float2(to_tf32(O8[na][2] * inv_hi), to_tf32(O8[na][3] * inv_hi));
    }
}

// ---------------------------------------------------------------------------
extern "C" void kernel_launch(void* const* d_in, const int* in_sizes, int n_in,
                              void* d_out, int out_size) {
    const float* x  = (const float*)d_in[0];
    const float* Wq = (const float*)d_in[1];
    const float* Wk = (const float*)d_in[2];
    const float* Wv = (const float*)d_in[3];
    const float* Wo = (const float*)d_in[4];

    float *Qp, *Kp, *Vp, *Ap, *Xr, *Wqr, *Wkr, *Wvr, *Wor;
    cudaGetSymbolAddress((void**)&Qp,  g_Q);
    cudaGetSymbolAddress((void**)&Kp,  g_K);
    cudaGetSymbolAddress((void**)&Vp,  g_V);
    cudaGetSymbolAddress((void**)&Ap,  g_A);
    cudaGetSymbolAddress((void**)&Xr,  g_Xr);
    cudaGetSymbolAddress((void**)&Wqr, g_Wq);
    cudaGetSymbolAddress((void**)&Wkr, g_Wk);
    cudaGetSymbolAddress((void**)&Wvr, g_Wv);
    cudaGetSymbolAddress((void**)&Wor, g_Wo);

    cudaFuncSetAttribute(gemm_tf32, cudaFuncAttributeMaxDynamicSharedMemorySize, GEMM_SMEM);
    cudaFuncSetAttribute(swa_attn_tc, cudaFuncAttributeMaxDynamicSharedMemorySize, AT_SMEM);

    const int nx4 = M_ROWS * D_MODEL / 4;
    const int nw4 = D_MODEL * D_MODEL / 4;
    round_tf32_kernel<<<nx4 / 256, 256>>>((const float4*)x,  (float4*)Xr,  nx4);
    round_tf32_kernel<<<nw4 / 256, 256>>>((const float4*)Wq, (float4*)Wqr, nw4);
    round_tf32_kernel<<<nw4 / 256, 256>>>((const float4*)Wk, (float4*)Wkr, nw4);
    round_tf32_kernel<<<nw4 / 256, 256>>>((const float4*)Wv, (float4*)Wvr, nw4);
    round_tf32_kernel<<<nw4 / 256, 256>>>((const float4*)Wo, (float4*)Wor, nw4);

    dim3 ggrid(D_MODEL / 128, M_ROWS / 256);  // (16, 32)
    gemm_tf32<<<ggrid, 256, GEMM_SMEM>>>(Xr, Wqr, Qp);
    gemm_tf32<<<ggrid, 256, GEMM_SMEM>>>(Xr, Wkr, Kp);
    gemm_tf32<<<ggrid, 256, GEMM_SMEM>>>(Xr, Wvr, Vp);

    swa_attn_tc<<<dim3(NBLK, N_HEADS, BATCH), 256, AT_SMEM>>>(Qp, Kp, Vp, Ap);

    gemm_tf32<<<ggrid, 256, GEMM_SMEM>>>(Ap, Wor, (float*)d_out);
}

// round 13
// speedup vs baseline: 1.2261x; 1.2261x over previous
#include <cuda_runtime.h>
#include <cstdint>

// Problem constants.
#define T_SEQ   4096
#define D_MODEL 2048
#define N_HEADS 32
#define D_HEAD  64
#define BATCH   2
#define M_ROWS  (BATCH * T_SEQ)   // 8192
#define NBLK    (T_SEQ / 128)     // 32

// Scratch (device globals: allocation-free rule).
__device__ float g_Q [M_ROWS * D_MODEL];
__device__ float g_K [M_ROWS * D_MODEL];
__device__ float g_V [M_ROWS * D_MODEL];
__device__ float g_A [M_ROWS * D_MODEL];
__device__ float g_Xr[M_ROWS * D_MODEL];
__device__ float g_Wq[D_MODEL * D_MODEL];
__device__ float g_Wk[D_MODEL * D_MODEL];
__device__ float g_Wv[D_MODEL * D_MODEL];
__device__ float g_Wo[D_MODEL * D_MODEL];

// ---------------------------------------------------------------------------
// Helpers
// ---------------------------------------------------------------------------
__device__ __forceinline__ uint32_t smem_u32(const void* p) {
    uint32_t a;
    asm("{ .reg .u64 t; cvta.to.shared.u64 t, %1; cvt.u32.u64 %0, t; }" : "=r"(a) : "l"(p));
    return a;
}
__device__ __forceinline__ void cp16(uint32_t s, const void* g) {
    asm volatile("cp.async.cg.shared.global [%0], [%1], 16;" :: "r"(s), "l"(g));
}
__device__ __forceinline__ float to_tf32(float x) {
    uint32_t u;
    asm("cvt.rna.tf32.f32 %0, %1;" : "=r"(u) : "f"(x));
    return __uint_as_float(u);
}
#define SW128(b) ((b) ^ (((b) >> 3) & 0x70))

__device__ __forceinline__ void ldsm4(uint32_t& a, uint32_t& b, uint32_t& c,
                                      uint32_t& d, uint32_t addr) {
    asm volatile("ldmatrix.sync.aligned.m8n8.x4.shared.b16 {%0,%1,%2,%3}, [%4];"
                 : "=r"(a), "=r"(b), "=r"(c), "=r"(d) : "r"(addr));
}
__device__ __forceinline__ void mma8(float* c, const uint32_t* a, const uint32_t* b) {
    asm volatile("mma.sync.aligned.m16n8k8.row.col.f32.tf32.tf32.f32 "
                 "{%0,%1,%2,%3},{%4,%5,%6,%7},{%8,%9},{%0,%1,%2,%3};"
                 : "+f"(c[0]), "+f"(c[1]), "+f"(c[2]), "+f"(c[3])
                 : "r"(a[0]), "r"(a[1]), "r"(a[2]), "r"(a[3]),
                   "r"(b[0]), "r"(b[1]));
}

// ---------------------------------------------------------------------------
// tf32 rounding prep: ONE launch for [X | Wq | Wk | Wv | Wo].
// ---------------------------------------------------------------------------
#define NX4 (M_ROWS * D_MODEL / 4)    // 4,194,304 float4
#define NW4 (D_MODEL * D_MODEL / 4)   // 1,048,576 float4
#define NTOT4 (NX4 + 4 * NW4)         // 8,388,608

__global__ void round_all_kernel(const float4* __restrict__ x,
                                 const float4* __restrict__ wq,
                                 const float4* __restrict__ wk,
                                 const float4* __restrict__ wv,
                                 const float4* __restrict__ wo,
                                 float4* __restrict__ xr,
                                 float4* __restrict__ wqr,
                                 float4* __restrict__ wkr,
                                 float4* __restrict__ wvr,
                                 float4* __restrict__ wor) {
    int i = blockIdx.x * blockDim.x + threadIdx.x;
    const float4* s;
    float4* d;
    int off;
    if (i < NX4)                 { s = x;  d = xr;  off = i; }
    else if (i < NX4 + NW4)      { s = wq; d = wqr; off = i - NX4; }
    else if (i < NX4 + 2 * NW4)  { s = wk; d = wkr; off = i - NX4 - NW4; }
    else if (i < NX4 + 3 * NW4)  { s = wv; d = wvr; off = i - NX4 - 2 * NW4; }
    else                         { s = wo; d = wor; off = i - NX4 - 3 * NW4; }
    float4 v = s[off];
    v.x = to_tf32(v.x); v.y = to_tf32(v.y);
    v.z = to_tf32(v.z); v.w = to_tf32(v.w);
    d[off] = v;
}

// ---------------------------------------------------------------------------
// C[m,n] = sum_k A[m,k]*B[n,k]  (A MxK, B NxK row-major, tf32-prerounded).
// R9 config: tile 128x128, BK=32, 8 warps (2x4), 3-stage cp.async, 2 CTA/SM.
// QKV-fused variant: B/C chosen from {Wq,Wk,Wv}/{Q,K,V} by blockIdx.x>>4.
// ---------------------------------------------------------------------------
#define BK 32
#define STAGE_BYTES 32768              // A 16KB + B 16KB
#define GEMM_SMEM (3 * STAGE_BYTES)    // 98304

__device__ __forceinline__ void gemm_load_chunk(uint32_t smb, int kc,
                                                const float* ag, const float* bg,
                                                uint32_t soff) {
    uint32_t ab = smb + (uint32_t)(kc % 3) * STAGE_BYTES;
    uint32_t bb = ab + 16384;
    const float* agp = ag + kc * BK;
    const float* bgp = bg + kc * BK;
#pragma unroll
    for (int i = 0; i < 4; i++) {
        cp16(ab + soff + i * 4096, agp + (size_t)i * 32 * D_MODEL);
        cp16(bb + soff + i * 4096, bgp + (size_t)i * 32 * D_MODEL);
    }
    asm volatile("cp.async.commit_group;" ::: "memory");
}

__device__ __forceinline__ void gemm_body(const float* __restrict__ A,
                                          const float* __restrict__ B,
                                          float* __restrict__ C,
                                          int bm, int bn) {
    extern __shared__ __align__(1024) char sm[];
    uint32_t smb = smem_u32(sm);
    const int tid = threadIdx.x;
    const int wid = tid >> 5, lane = tid & 31;
    const int wm = wid & 1;
    const int wn = wid >> 1;

    const int r0 = tid >> 3;
    const int c4 = tid & 7;
    const float* ag = A + (size_t)(bm + r0) * D_MODEL + c4 * 4;
    const float* bg = B + (size_t)(bn + r0) * D_MODEL + c4 * 4;
    const uint32_t soff = SW128((uint32_t)(r0 * 128 + c4 * 16));

    const int lg = lane >> 3, lr = lane & 7;
    const int a_row = (lg & 1) * 8 + lr;
    const int a_k16 = (lg >> 1) * 16;
    const int b_row = (lg >> 1) * 8 + lr;
    const int b_k16 = (lg & 1) * 16;

    float  Cacc[4][4][4];
    uint32_t Af[4][4], Bf[4][2];
#pragma unroll
    for (int i = 0; i < 4; i++)
#pragma unroll
        for (int j = 0; j < 4; j++)
#pragma unroll
            for (int q = 0; q < 4; q++) Cacc[i][j][q] = 0.f;

    gemm_load_chunk(smb, 0, ag, bg, soff);
    gemm_load_chunk(smb, 1, ag, bg, soff);

    const int NCHUNK = D_MODEL / BK;  // 64
    for (int c = 0; c < NCHUNK; c++) {
        if (c == NCHUNK - 1)
            asm volatile("cp.async.wait_group 0;" ::: "memory");
        else
            asm volatile("cp.async.wait_group 1;" ::: "memory");
        __syncthreads();
        if (c + 2 < NCHUNK) gemm_load_chunk(smb, c + 2, ag, bg, soff);

        uint32_t sa = smb + (uint32_t)(c % 3) * STAGE_BYTES;
        uint32_t sb = sa + 16384;
#pragma unroll
        for (int ks = 0; ks < 4; ks++) {
            const int kb = ks * 32;
#pragma unroll
            for (int ma = 0; ma < 4; ma++) {
                int row = wm * 64 + ma * 16 + a_row;
                uint32_t off = (uint32_t)(row * 128 + ((row & 7) * 16 ^ (kb + a_k16)));
                ldsm4(Af[ma][0], Af[ma][1], Af[ma][2], Af[ma][3], sa + off);
            }
#pragma unroll
            for (int p = 0; p < 2; p++) {
                int n = wn * 32 + p * 16 + b_row;
                uint32_t off = (uint32_t)(n * 128 + ((n & 7) * 16 ^ (kb + b_k16)));
                ldsm4(Bf[p * 2][0], Bf[p * 2][1], Bf[p * 2 + 1][0], Bf[p * 2 + 1][1],
                      sb + off);
            }
#pragma unroll
            for (int ma = 0; ma < 4; ma++)
#pragma unroll
                for (int na = 0; na < 4; na++)
                    mma8(Cacc[ma][na], Af[ma], Bf[na]);
        }
        // No trailing __syncthreads(): next iteration's top sync orders reuse.
    }

    const int er = lane >> 2, ec = (lane & 3) * 2;
#pragma unroll
    for (int ma = 0; ma < 4; ma++) {
        int grow = bm + wm * 64 + ma * 16 + er;
#pragma unroll
        for (int na = 0; na < 4; na++) {
            int gcol = bn + wn * 32 + na * 8 + ec;
            float* cp0 = C + (size_t)grow * D_MODEL + gcol;
            float* cp1 = C + (size_t)(grow + 8) * D_MODEL + gcol;
            *(float2*)cp0 = make_float2(Cacc[ma][na][0], Cacc[ma][na][1]);
            *(float2*)cp1 = make_float2(Cacc[ma][na][2], Cacc[ma][na][3]);
        }
    }
}

// Fused QKV: grid (48, 64); blockIdx.x>>4 selects {Wq->Q, Wk->K, Wv->V}.
__global__ __launch_bounds__(256, 2) void gemm_qkv(const float* __restrict__ A,
                                                   const float* __restrict__ Bq,
                                                   const float* __restrict__ Bk,
                                                   const float* __restrict__ Bv,
                                                   float* __restrict__ Cq,
                                                   float* __restrict__ Ck,
                                                   float* __restrict__ Cv) {
    const int sel = blockIdx.x >> 4;
    const int bn = (blockIdx.x & 15) * 128;
    const int bm = blockIdx.y * 128;
    const float* B = (sel == 0) ? Bq : (sel == 1) ? Bk : Bv;
    float* C = (sel == 0) ? Cq : (sel == 1) ? Ck : Cv;
    gemm_body(A, B, C, bm, bn);
}

__global__ __launch_bounds__(256, 2) void gemm_tf32(const float* __restrict__ A,
                                                    const float* __restrict__ B,
                                                    float* __restrict__ C) {
    gemm_body(A, B, C, blockIdx.y * 128, blockIdx.x * 128);
}

// ---------------------------------------------------------------------------
// Tensor-core fused sliding-window attention (unchanged from round 9).
// ---------------------------------------------------------------------------
#define AT_Q 0
#define AT_K 32768
#define AT_V 98304
#define AT_SMEM 163840

__global__ __launch_bounds__(256, 1) void swa_attn_tc(const float* __restrict__ Q,
                                                      const float* __restrict__ Kmat,
                                                      const float* __restrict__ V,
                                                      float* __restrict__ O) {
    extern __shared__ __align__(1024) char sm[];
    uint32_t smb = smem_u32(sm);
    float* smf = (float*)sm;

    const int tid  = threadIdx.x;
    const int wid  = tid >> 5, lane = tid & 31;
    const int iblk = blockIdx.x;
    const int h    = blockIdx.y;
    const int b    = blockIdx.z;
    const int row0 = b * T_SEQ + iblk * 128;
    const int colh = h * D_HEAD;
    const int bbase = b * T_SEQ;

    for (int idx = tid; idx < 128 * 16; idx += 256) {
        int r = idx >> 4, d4 = idx & 15;
        int panel = d4 >> 3, x = (d4 & 7) * 16;
        cp16(smb + AT_Q + panel * 16384 + r * 128 + (x ^ ((r & 7) * 16)),
             Q + (size_t)(row0 + r) * D_MODEL + colh + d4 * 4);
    }
    asm volatile("cp.async.commit_group;" ::: "memory");

    {
        int krow = row0 - 128 + tid;
        if (krow < bbase) krow = bbase;
        const float* kg = Kmat + (size_t)krow * D_MODEL + colh;
        uint32_t kbase = smb + AT_K + tid * 128;
#pragma unroll
        for (int d4 = 0; d4 < 16; d4++) {
            float4 v = *(const float4*)(kg + d4 * 4);
            v.x = to_tf32(v.x); v.y = to_tf32(v.y);
            v.z = to_tf32(v.z); v.w = to_tf32(v.w);
            int panel = d4 >> 3, x = (d4 & 7) * 16;
            *(float4*)(sm + (kbase - smb) + panel * 32768 + (x ^ ((tid & 7) * 16))) = v;
        }
    }
    {
        int krow = row0 - 128 + tid;
        if (krow < bbase) krow = bbase;
        const float* vg = V + (size_t)krow * D_MODEL + colh;
        const int kp = tid >> 5;
        const int kx = (tid & 31) * 4;
        const int vbase = (AT_V >> 2) + kp * 2048;
#pragma unroll
        for (int d4 = 0; d4 < 16; d4++) {
            float4 v = *(const float4*)(vg + d4 * 4);
            int d = d4 * 4;
            smf[vbase + (d + 0) * 32 + (((uint32_t)kx ^ (((d + 0) & 7) * 16)) >> 2)] = to_tf32(v.x);
            smf[vbase + (d + 1) * 32 + (((uint32_t)kx ^ (((d + 1) & 7) * 16)) >> 2)] = to_tf32(v.y);
            smf[vbase + (d + 2) * 32 + (((uint32_t)kx ^ (((d + 2) & 7) * 16)) >> 2)] = to_tf32(v.z);
            smf[vbase + (d + 3) * 32 + (((uint32_t)kx ^ (((d + 3) & 7) * 16)) >> 2)] = to_tf32(v.w);
        }
    }
    asm volatile("cp.async.wait_group 0;" ::: "memory");
    __syncthreads();

    const int lg = lane >> 3, lr = lane & 7;
    const int a_row = (lg & 1) * 8 + lr;
    const int a_k16 = (lg >> 1) * 16;
    const int b_row = (lg >> 1) * 8 + lr;
    const int b_k16 = (lg & 1) * 16;
    const int q4 = lane & 3;

    float P[32][4];
#pragma unroll
    for (int i = 0; i < 32; i++)
#pragma unroll
        for (int j = 0; j < 4; j++) P[i][j] = 0.f;

    {
        const int arow_g = wid * 16 + a_row;
        uint32_t Ar[4], Ahi[4], Alo[4], B0, B1, B2, B3;
#pragma unroll
        for (int ks = 0; ks < 8; ks++) {
            int kbyte = ks * 32 + a_k16;
            ldsm4(Ar[0], Ar[1], Ar[2], Ar[3],
                  smb + AT_Q + (kbyte >> 7) * 16384 + arow_g * 128 +
                  ((kbyte & 127) ^ ((arow_g & 7) * 16)));
#pragma unroll
            for (int i = 0; i < 4; i++) {
                float x = __uint_as_float(Ar[i]);
                float hi = to_tf32(x);
                Ahi[i] = __float_as_uint(hi);
                Alo[i] = __float_as_uint(to_tf32(x - hi));
            }
            int kbb = ks * 32 + b_k16;
            uint32_t pb = smb + AT_K + (kbb >> 7) * 32768;
            int xb = kbb & 127;
#pragma unroll
            for (int np = 0; np < 16; np++) {
                int c = np * 16 + b_row;
                ldsm4(B0, B1, B2, B3, pb + c * 128 + (xb ^ ((c & 7) * 16)));
                uint32_t bf0[2] = {B0, B1}, bf1[2] = {B2, B3};
                mma8(P[2 * np], Ahi, bf0);
                mma8(P[2 * np], Alo, bf0);
                mma8(P[2 * np + 1], Ahi, bf1);
                mma8(P[2 * np + 1], Alo, bf1);
            }
        }
    }

    const int r_lo = wid * 16 + (lane >> 2);
    const int r_hi = r_lo + 8;
    const float scale = 0.125f;
    float m_lo = -1e30f, m_hi = -1e30f;
#pragma unroll
    for (int na = 0; na < 32; na++) {
        int c0 = 8 * na + 2 * q4, c1 = c0 + 1;
        bool ok0 = (iblk > 0 || c0 >= 128);
        bool ok1 = (iblk > 0 || c1 >= 128);
        float s0 = (ok0 && c0 >= r_lo && c0 <= r_lo + 128) ? P[na][0] * scale : -1e30f;
        float s1 = (ok1 && c1 >= r_lo && c1 <= r_lo + 128) ? P[na][1] * scale : -1e30f;
        float s2 = (ok0 && c0 >= r_hi && c0 <= r_hi + 128) ? P[na][2] * scale : -1e30f;
        float s3 = (ok1 && c1 >= r_hi && c1 <= r_hi + 128) ? P[na][3] * scale : -1e30f;
        P[na][0] = s0; P[na][1] = s1; P[na][2] = s2; P[na][3] = s3;
        m_lo = fmaxf(m_lo, fmaxf(s0, s1));
        m_hi = fmaxf(m_hi, fmaxf(s2, s3));
    }
    m_lo = fmaxf(m_lo, __shfl_xor_sync(0xffffffff, m_lo, 1));
    m_lo = fmaxf(m_lo, __shfl_xor_sync(0xffffffff, m_lo, 2));
    m_hi = fmaxf(m_hi, __shfl_xor_sync(0xffffffff, m_hi, 1));
    m_hi = fmaxf(m_hi, __shfl_xor_sync(0xffffffff, m_hi, 2));
    float s_lo = 0.f, s_hi = 0.f;
#pragma unroll
    for (int na = 0; na < 32; na++) {
        float e0 = __expf(P[na][0] - m_lo);
        float e1 = __expf(P[na][1] - m_lo);
        float e2 = __expf(P[na][2] - m_hi);
        float e3 = __expf(P[na][3] - m_hi);
        P[na][0] = e0; P[na][1] = e1; P[na][2] = e2; P[na][3] = e3;
        s_lo += e0 + e1; s_hi += e2 + e3;
    }
    s_lo += __shfl_xor_sync(0xffffffff, s_lo, 1);
    s_lo += __shfl_xor_sync(0xffffffff, s_lo, 2);
    s_hi += __shfl_xor_sync(0xffffffff, s_hi, 1);
    s_hi += __shfl_xor_sync(0xffffffff, s_hi, 2);
    const float inv_lo = 1.f / s_lo, inv_hi = 1.f / s_hi;

    float O8[8][4];
#pragma unroll
    for (int i = 0; i < 8; i++)
#pragma unroll
        for (int j = 0; j < 4; j++) O8[i][j] = 0.f;

    const int src1 = (lane & ~3) | (q4 >> 1);
    const int src2 = src1 + 2;
#pragma unroll
    for (int ks = 0; ks < 32; ks++) {
        float u, v, a0f, a1f, a2f, a3f;
        u = __shfl_sync(0xffffffff, P[ks][0], src1);
        v = __shfl_sync(0xffffffff, P[ks][1], src1);
        a0f = (q4 & 1) ? v : u;
        u = __shfl_sync(0xffffffff, P[ks][2], src1);
        v = __shfl_sync(0xffffffff, P[ks][3], src1);
        a1f = (q4 & 1) ? v : u;
        u = __shfl_sync(0xffffffff, P[ks][0], src2);
        v = __shfl_sync(0xffffffff, P[ks][1], src2);
        a2f = (q4 & 1) ? v : u;
        u = __shfl_sync(0xffffffff, P[ks][2], src2);
        v = __shfl_sync(0xffffffff, P[ks][3], src2);
        a3f = (q4 & 1) ? v : u;
        uint32_t Au[4] = {__float_as_uint(to_tf32(a0f)), __float_as_uint(to_tf32(a1f)),
                          __float_as_uint(to_tf32(a2f)), __float_as_uint(to_tf32(a3f))};
        uint32_t vp = smb + AT_V + (ks >> 2) * 8192;
        int kb2 = (ks & 3) * 32 + b_k16;
        uint32_t B0, B1, B2, B3;
#pragma unroll
        for (int p = 0; p < 4; p++) {
            int d = p * 16 + b_row;
            ldsm4(B0, B1, B2, B3, vp + d * 128 + (kb2 ^ ((d & 7) * 16)));
            uint32_t bf0[2] = {B0, B1}, bf1[2] = {B2, B3};
            mma8(O8[2 * p], Au, bf0);
            mma8(O8[2 * p + 1], Au, bf1);
        }
    }

#pragma unroll
    for (int na = 0; na < 8; na++) {
        int gcol = colh + 8 * na + 2 * q4;
        float* o0 = O + (size_t)(row0 + r_lo) * D_MODEL + gcol;
        float* o1 = O + (size_t)(row0 + r_hi) * D_MODEL + gcol;
        *(float2*)o0 = make_float2(to_tf32(O8[na][0] * inv_lo), to_tf32(O8[na][1] * inv_lo));
        *(float2*)o1 = make_float2(to_tf32(O8[na][2] * inv_hi), to_tf32(O8[na][3] * inv_hi));
    }
}

// ---------------------------------------------------------------------------
extern "C" void kernel_launch(void* const* d_in, const int* in_sizes, int n_in,
                              void* d_out, int out_size) {
    const float* x  = (const float*)d_in[0];
    const float* Wq = (const float*)d_in[1];
    const float* Wk = (const float*)d_in[2];
    const float* Wv = (const float*)d_in[3];
    const float* Wo = (const float*)d_in[4];

    float *Qp, *Kp, *Vp, *Ap, *Xr, *Wqr, *Wkr, *Wvr, *Wor;
    cudaGetSymbolAddress((void**)&Qp,  g_Q);
    cudaGetSymbolAddress((void**)&Kp,  g_K);
    cudaGetSymbolAddress((void**)&Vp,  g_V);
    cudaGetSymbolAddress((void**)&Ap,  g_A);
    cudaGetSymbolAddress((void**)&Xr,  g_Xr);
    cudaGetSymbolAddress((void**)&Wqr, g_Wq);
    cudaGetSymbolAddress((void**)&Wkr, g_Wk);
    cudaGetSymbolAddress((void**)&Wvr, g_Wv);
    cudaGetSymbolAddress((void**)&Wor, g_Wo);

    cudaFuncSetAttribute(gemm_qkv,  cudaFuncAttributeMaxDynamicSharedMemorySize, GEMM_SMEM);
    cudaFuncSetAttribute(gemm_tf32, cudaFuncAttributeMaxDynamicSharedMemorySize, GEMM_SMEM);
    cudaFuncSetAttribute(swa_attn_tc, cudaFuncAttributeMaxDynamicSharedMemorySize, AT_SMEM);

    round_all_kernel<<<NTOT4 / 256, 256>>>(
        (const float4*)x, (const float4*)Wq, (const float4*)Wk,
        (const float4*)Wv, (const float4*)Wo,
        (float4*)Xr, (float4*)Wqr, (float4*)Wkr, (float4*)Wvr, (float4*)Wor);

    gemm_qkv<<<dim3(48, M_ROWS / 128), 256, GEMM_SMEM>>>(Xr, Wqr, Wkr, Wvr, Qp, Kp, Vp);

    swa_attn_tc<<<dim3(NBLK, N_HEADS, BATCH), 256, AT_SMEM>>>(Qp, Kp, Vp, Ap);

    gemm_tf32<<<dim3(16, M_ROWS / 128), 256, GEMM_SMEM>>>(Ap, Wor, (float*)d_out);
}

// round 14
// speedup vs baseline: 1.2597x; 1.0274x over previous
#include <cuda_runtime.h>
#include <cstdint>

// Problem constants.
#define T_SEQ   4096
#define D_MODEL 2048
#define N_HEADS 32
#define D_HEAD  64
#define BATCH   2
#define M_ROWS  (BATCH * T_SEQ)   // 8192
#define NBLK    (T_SEQ / 128)     // 32

// Scratch (device globals: allocation-free rule).
__device__ float g_Q [M_ROWS * D_MODEL];
__device__ float g_K [M_ROWS * D_MODEL];
__device__ float g_V [M_ROWS * D_MODEL];
__device__ float g_A [M_ROWS * D_MODEL];
__device__ float g_Xr[M_ROWS * D_MODEL];
__device__ float g_Wq[D_MODEL * D_MODEL];
__device__ float g_Wk[D_MODEL * D_MODEL];
__device__ float g_Wv[D_MODEL * D_MODEL];
__device__ float g_Wo[D_MODEL * D_MODEL];

// ---------------------------------------------------------------------------
// Helpers
// ---------------------------------------------------------------------------
__device__ __forceinline__ uint32_t smem_u32(const void* p) {
    uint32_t a;
    asm("{ .reg .u64 t; cvta.to.shared.u64 t, %1; cvt.u32.u64 %0, t; }" : "=r"(a) : "l"(p));
    return a;
}
__device__ __forceinline__ void cp16(uint32_t s, const void* g) {
    asm volatile("cp.async.cg.shared.global [%0], [%1], 16;" :: "r"(s), "l"(g));
}
__device__ __forceinline__ float to_tf32(float x) {
    uint32_t u;
    asm("cvt.rna.tf32.f32 %0, %1;" : "=r"(u) : "f"(x));
    return __uint_as_float(u);
}
#define SW128(b) ((b) ^ (((b) >> 3) & 0x70))

__device__ __forceinline__ void ldsm4(uint32_t& a, uint32_t& b, uint32_t& c,
                                      uint32_t& d, uint32_t addr) {
    asm volatile("ldmatrix.sync.aligned.m8n8.x4.shared.b16 {%0,%1,%2,%3}, [%4];"
                 : "=r"(a), "=r"(b), "=r"(c), "=r"(d) : "r"(addr));
}
__device__ __forceinline__ void mma8(float* c, const uint32_t* a, const uint32_t* b) {
    asm volatile("mma.sync.aligned.m16n8k8.row.col.f32.tf32.tf32.f32 "
                 "{%0,%1,%2,%3},{%4,%5,%6,%7},{%8,%9},{%0,%1,%2,%3};"
                 : "+f"(c[0]), "+f"(c[1]), "+f"(c[2]), "+f"(c[3])
                 : "r"(a[0]), "r"(a[1]), "r"(a[2]), "r"(a[3]),
                   "r"(b[0]), "r"(b[1]));
}

// ---------------------------------------------------------------------------
// tf32 rounding prep: ONE launch for [X | Wq | Wk | Wv | Wo].
// ---------------------------------------------------------------------------
#define NX4 (M_ROWS * D_MODEL / 4)
#define NW4 (D_MODEL * D_MODEL / 4)
#define NTOT4 (NX4 + 4 * NW4)

__global__ void round_all_kernel(const float4* __restrict__ x,
                                 const float4* __restrict__ wq,
                                 const float4* __restrict__ wk,
                                 const float4* __restrict__ wv,
                                 const float4* __restrict__ wo,
                                 float4* __restrict__ xr,
                                 float4* __restrict__ wqr,
                                 float4* __restrict__ wkr,
                                 float4* __restrict__ wvr,
                                 float4* __restrict__ wor) {
    int i = blockIdx.x * blockDim.x + threadIdx.x;
    const float4* s;
    float4* d;
    int off;
    if (i < NX4)                 { s = x;  d = xr;  off = i; }
    else if (i < NX4 + NW4)      { s = wq; d = wqr; off = i - NX4; }
    else if (i < NX4 + 2 * NW4)  { s = wk; d = wkr; off = i - NX4 - NW4; }
    else if (i < NX4 + 3 * NW4)  { s = wv; d = wvr; off = i - NX4 - 2 * NW4; }
    else                         { s = wo; d = wor; off = i - NX4 - 3 * NW4; }
    float4 v = s[off];
    v.x = to_tf32(v.x); v.y = to_tf32(v.y);
    v.z = to_tf32(v.z); v.w = to_tf32(v.w);
    d[off] = v;
}

// ---------------------------------------------------------------------------
// GEMM (R13 config, unchanged): tile 128x128, BK=32, 8 warps, 3-stage, 2 CTA/SM.
// ---------------------------------------------------------------------------
#define BK 32
#define STAGE_BYTES 32768
#define GEMM_SMEM (3 * STAGE_BYTES)

__device__ __forceinline__ void gemm_load_chunk(uint32_t smb, int kc,
                                                const float* ag, const float* bg,
                                                uint32_t soff) {
    uint32_t ab = smb + (uint32_t)(kc % 3) * STAGE_BYTES;
    uint32_t bb = ab + 16384;
    const float* agp = ag + kc * BK;
    const float* bgp = bg + kc * BK;
#pragma unroll
    for (int i = 0; i < 4; i++) {
        cp16(ab + soff + i * 4096, agp + (size_t)i * 32 * D_MODEL);
        cp16(bb + soff + i * 4096, bgp + (size_t)i * 32 * D_MODEL);
    }
    asm volatile("cp.async.commit_group;" ::: "memory");
}

__device__ __forceinline__ void gemm_body(const float* __restrict__ A,
                                          const float* __restrict__ B,
                                          float* __restrict__ C,
                                          int bm, int bn) {
    extern __shared__ __align__(1024) char sm[];
    uint32_t smb = smem_u32(sm);
    const int tid = threadIdx.x;
    const int wid = tid >> 5, lane = tid & 31;
    const int wm = wid & 1;
    const int wn = wid >> 1;

    const int r0 = tid >> 3;
    const int c4 = tid & 7;
    const float* ag = A + (size_t)(bm + r0) * D_MODEL + c4 * 4;
    const float* bg = B + (size_t)(bn + r0) * D_MODEL + c4 * 4;
    const uint32_t soff = SW128((uint32_t)(r0 * 128 + c4 * 16));

    const int lg = lane >> 3, lr = lane & 7;
    const int a_row = (lg & 1) * 8 + lr;
    const int a_k16 = (lg >> 1) * 16;
    const int b_row = (lg >> 1) * 8 + lr;
    const int b_k16 = (lg & 1) * 16;

    float  Cacc[4][4][4];
    uint32_t Af[4][4], Bf[4][2];
#pragma unroll
    for (int i = 0; i < 4; i++)
#pragma unroll
        for (int j = 0; j < 4; j++)
#pragma unroll
            for (int q = 0; q < 4; q++) Cacc[i][j][q] = 0.f;

    gemm_load_chunk(smb, 0, ag, bg, soff);
    gemm_load_chunk(smb, 1, ag, bg, soff);

    const int NCHUNK = D_MODEL / BK;  // 64
    for (int c = 0; c < NCHUNK; c++) {
        if (c == NCHUNK - 1)
            asm volatile("cp.async.wait_group 0;" ::: "memory");
        else
            asm volatile("cp.async.wait_group 1;" ::: "memory");
        __syncthreads();
        if (c + 2 < NCHUNK) gemm_load_chunk(smb, c + 2, ag, bg, soff);

        uint32_t sa = smb + (uint32_t)(c % 3) * STAGE_BYTES;
        uint32_t sb = sa + 16384;
#pragma unroll
        for (int ks = 0; ks < 4; ks++) {
            const int kb = ks * 32;
#pragma unroll
            for (int ma = 0; ma < 4; ma++) {
                int row = wm * 64 + ma * 16 + a_row;
                uint32_t off = (uint32_t)(row * 128 + ((row & 7) * 16 ^ (kb + a_k16)));
                ldsm4(Af[ma][0], Af[ma][1], Af[ma][2], Af[ma][3], sa + off);
            }
#pragma unroll
            for (int p = 0; p < 2; p++) {
                int n = wn * 32 + p * 16 + b_row;
                uint32_t off = (uint32_t)(n * 128 + ((n & 7) * 16 ^ (kb + b_k16)));
                ldsm4(Bf[p * 2][0], Bf[p * 2][1], Bf[p * 2 + 1][0], Bf[p * 2 + 1][1],
                      sb + off);
            }
#pragma unroll
            for (int ma = 0; ma < 4; ma++)
#pragma unroll
                for (int na = 0; na < 4; na++)
                    mma8(Cacc[ma][na], Af[ma], Bf[na]);
        }
    }

    const int er = lane >> 2, ec = (lane & 3) * 2;
#pragma unroll
    for (int ma = 0; ma < 4; ma++) {
        int grow = bm + wm * 64 + ma * 16 + er;
#pragma unroll
        for (int na = 0; na < 4; na++) {
            int gcol = bn + wn * 32 + na * 8 + ec;
            float* cp0 = C + (size_t)grow * D_MODEL + gcol;
            float* cp1 = C + (size_t)(grow + 8) * D_MODEL + gcol;
            *(float2*)cp0 = make_float2(Cacc[ma][na][0], Cacc[ma][na][1]);
            *(float2*)cp1 = make_float2(Cacc[ma][na][2], Cacc[ma][na][3]);
        }
    }
}

__global__ __launch_bounds__(256, 2) void gemm_qkv(const float* __restrict__ A,
                                                   const float* __restrict__ Bq,
                                                   const float* __restrict__ Bk,
                                                   const float* __restrict__ Bv,
                                                   float* __restrict__ Cq,
                                                   float* __restrict__ Ck,
                                                   float* __restrict__ Cv) {
    const int sel = blockIdx.x >> 4;
    const int bn = (blockIdx.x & 15) * 128;
    const int bm = blockIdx.y * 128;
    const float* B = (sel == 0) ? Bq : (sel == 1) ? Bk : Bv;
    float* C = (sel == 0) ? Cq : (sel == 1) ? Ck : Cv;
    gemm_body(A, B, C, bm, bn);
}

__global__ __launch_bounds__(256, 2) void gemm_tf32(const float* __restrict__ A,
                                                    const float* __restrict__ B,
                                                    float* __restrict__ C) {
    gemm_body(A, B, C, blockIdx.y * 128, blockIdx.x * 128);
}

// ---------------------------------------------------------------------------
// Tensor-core fused sliding-window attention with STATIC BAND SKIP.
// Warp w's rows span [16w, 16w+15] -> valid window cols [16w, 16w+143]:
//   QK  K-atoms (16-wide): np in [w, w+8]          (9 of 16)
//   P/PV atoms   (8-wide): global ks in [2w, 2w+17] (18 of 32)
// Skipped atoms previously contributed exact 0.0f -> bit-identical results.
// ---------------------------------------------------------------------------
#define AT_Q 0
#define AT_K 32768
#define AT_V 98304
#define AT_SMEM 163840
#define NPA 18   // valid 8-wide P atoms per warp

__global__ __launch_bounds__(256, 1) void swa_attn_tc(const float* __restrict__ Q,
                                                      const float* __restrict__ Kmat,
                                                      const float* __restrict__ V,
                                                      float* __restrict__ O) {
    extern __shared__ __align__(1024) char sm[];
    uint32_t smb = smem_u32(sm);
    float* smf = (float*)sm;

    const int tid  = threadIdx.x;
    const int wid  = tid >> 5, lane = tid & 31;
    const int iblk = blockIdx.x;
    const int h    = blockIdx.y;
    const int b    = blockIdx.z;
    const int row0 = b * T_SEQ + iblk * 128;
    const int colh = h * D_HEAD;
    const int bbase = b * T_SEQ;

    for (int idx = tid; idx < 128 * 16; idx += 256) {
        int r = idx >> 4, d4 = idx & 15;
        int panel = d4 >> 3, x = (d4 & 7) * 16;
        cp16(smb + AT_Q + panel * 16384 + r * 128 + (x ^ ((r & 7) * 16)),
             Q + (size_t)(row0 + r) * D_MODEL + colh + d4 * 4);
    }
    asm volatile("cp.async.commit_group;" ::: "memory");

    {
        int krow = row0 - 128 + tid;
        if (krow < bbase) krow = bbase;
        const float* kg = Kmat + (size_t)krow * D_MODEL + colh;
        uint32_t kbase = smb + AT_K + tid * 128;
#pragma unroll
        for (int d4 = 0; d4 < 16; d4++) {
            float4 v = *(const float4*)(kg + d4 * 4);
            v.x = to_tf32(v.x); v.y = to_tf32(v.y);
            v.z = to_tf32(v.z); v.w = to_tf32(v.w);
            int panel = d4 >> 3, x = (d4 & 7) * 16;
            *(float4*)(sm + (kbase - smb) + panel * 32768 + (x ^ ((tid & 7) * 16))) = v;
        }
    }
    {
        int krow = row0 - 128 + tid;
        if (krow < bbase) krow = bbase;
        const float* vg = V + (size_t)krow * D_MODEL + colh;
        const int kp = tid >> 5;
        const int kx = (tid & 31) * 4;
        const int vbase = (AT_V >> 2) + kp * 2048;
#pragma unroll
        for (int d4 = 0; d4 < 16; d4++) {
            float4 v = *(const float4*)(vg + d4 * 4);
            int d = d4 * 4;
            smf[vbase + (d + 0) * 32 + (((uint32_t)kx ^ (((d + 0) & 7) * 16)) >> 2)] = to_tf32(v.x);
            smf[vbase + (d + 1) * 32 + (((uint32_t)kx ^ (((d + 1) & 7) * 16)) >> 2)] = to_tf32(v.y);
            smf[vbase + (d + 2) * 32 + (((uint32_t)kx ^ (((d + 2) & 7) * 16)) >> 2)] = to_tf32(v.z);
            smf[vbase + (d + 3) * 32 + (((uint32_t)kx ^ (((d + 3) & 7) * 16)) >> 2)] = to_tf32(v.w);
        }
    }
    asm volatile("cp.async.wait_group 0;" ::: "memory");
    __syncthreads();

    const int lg = lane >> 3, lr = lane & 7;
    const int a_row = (lg & 1) * 8 + lr;
    const int a_k16 = (lg >> 1) * 16;
    const int b_row = (lg >> 1) * 8 + lr;
    const int b_k16 = (lg & 1) * 16;
    const int q4 = lane & 3;

    // ---- QK^T (2-pass split), band atoms only: P[j] = atom (2*wid + j) ----
    float P[NPA][4];
#pragma unroll
    for (int i = 0; i < NPA; i++)
#pragma unroll
        for (int j = 0; j < 4; j++) P[i][j] = 0.f;

    {
        const int arow_g = wid * 16 + a_row;
        uint32_t Ar[4], Ahi[4], Alo[4], B0, B1, B2, B3;
#pragma unroll
        for (int ks = 0; ks < 8; ks++) {
            int kbyte = ks * 32 + a_k16;
            ldsm4(Ar[0], Ar[1], Ar[2], Ar[3],
                  smb + AT_Q + (kbyte >> 7) * 16384 + arow_g * 128 +
                  ((kbyte & 127) ^ ((arow_g & 7) * 16)));
#pragma unroll
            for (int i = 0; i < 4; i++) {
                float x = __uint_as_float(Ar[i]);
                float hi = to_tf32(x);
                Ahi[i] = __float_as_uint(hi);
                Alo[i] = __float_as_uint(to_tf32(x - hi));
            }
            int kbb = ks * 32 + b_k16;
            uint32_t pb = smb + AT_K + (kbb >> 7) * 32768;
            int xb = kbb & 127;
#pragma unroll
            for (int dnp = 0; dnp < 9; dnp++) {       // np = wid + dnp
                int c = (wid + dnp) * 16 + b_row;
                ldsm4(B0, B1, B2, B3, pb + c * 128 + (xb ^ ((c & 7) * 16)));
                uint32_t bf0[2] = {B0, B1}, bf1[2] = {B2, B3};
                mma8(P[2 * dnp], Ahi, bf0);
                mma8(P[2 * dnp], Alo, bf0);
                mma8(P[2 * dnp + 1], Ahi, bf1);
                mma8(P[2 * dnp + 1], Alo, bf1);
            }
        }
    }

    // ---- Mask + softmax over the 18 band atoms ----
    const int r_lo = wid * 16 + (lane >> 2);
    const int r_hi = r_lo + 8;
    const float scale = 0.125f;
    float m_lo = -1e30f, m_hi = -1e30f;
#pragma unroll
    for (int j = 0; j < NPA; j++) {
        int c0 = 8 * (2 * wid + j) + 2 * q4, c1 = c0 + 1;
        bool ok0 = (iblk > 0 || c0 >= 128);
        bool ok1 = (iblk > 0 || c1 >= 128);
        float s0 = (ok0 && c0 >= r_lo && c0 <= r_lo + 128) ? P[j][0] * scale : -1e30f;
        float s1 = (ok1 && c1 >= r_lo && c1 <= r_lo + 128) ? P[j][1] * scale : -1e30f;
        float s2 = (ok0 && c0 >= r_hi && c0 <= r_hi + 128) ? P[j][2] * scale : -1e30f;
        float s3 = (ok1 && c1 >= r_hi && c1 <= r_hi + 128) ? P[j][3] * scale : -1e30f;
        P[j][0] = s0; P[j][1] = s1; P[j][2] = s2; P[j][3] = s3;
        m_lo = fmaxf(m_lo, fmaxf(s0, s1));
        m_hi = fmaxf(m_hi, fmaxf(s2, s3));
    }
    m_lo = fmaxf(m_lo, __shfl_xor_sync(0xffffffff, m_lo, 1));
    m_lo = fmaxf(m_lo, __shfl_xor_sync(0xffffffff, m_lo, 2));
    m_hi = fmaxf(m_hi, __shfl_xor_sync(0xffffffff, m_hi, 1));
    m_hi = fmaxf(m_hi, __shfl_xor_sync(0xffffffff, m_hi, 2));
    float s_lo = 0.f, s_hi = 0.f;
#pragma unroll
    for (int j = 0; j < NPA; j++) {
        float e0 = __expf(P[j][0] - m_lo);
        float e1 = __expf(P[j][1] - m_lo);
        float e2 = __expf(P[j][2] - m_hi);
        float e3 = __expf(P[j][3] - m_hi);
        P[j][0] = e0; P[j][1] = e1; P[j][2] = e2; P[j][3] = e3;
        s_lo += e0 + e1; s_hi += e2 + e3;
    }
    s_lo += __shfl_xor_sync(0xffffffff, s_lo, 1);
    s_lo += __shfl_xor_sync(0xffffffff, s_lo, 2);
    s_hi += __shfl_xor_sync(0xffffffff, s_hi, 1);
    s_hi += __shfl_xor_sync(0xffffffff, s_hi, 2);
    const float inv_lo = 1.f / s_lo, inv_hi = 1.f / s_hi;

    // ---- PV over band atoms: global ks = 2*wid + j ----
    float O8[8][4];
#pragma unroll
    for (int i = 0; i < 8; i++)
#pragma unroll
        for (int j = 0; j < 4; j++) O8[i][j] = 0.f;

    const int src1 = (lane & ~3) | (q4 >> 1);
    const int src2 = src1 + 2;
#pragma unroll
    for (int j = 0; j < NPA; j++) {
        const int ks = 2 * wid + j;
        float u, v, a0f, a1f, a2f, a3f;
        u = __shfl_sync(0xffffffff, P[j][0], src1);
        v = __shfl_sync(0xffffffff, P[j][1], src1);
        a0f = (q4 & 1) ? v : u;
        u = __shfl_sync(0xffffffff, P[j][2], src1);
        v = __shfl_sync(0xffffffff, P[j][3], src1);
        a1f = (q4 & 1) ? v : u;
        u = __shfl_sync(0xffffffff, P[j][0], src2);
        v = __shfl_sync(0xffffffff, P[j][1], src2);
        a2f = (q4 & 1) ? v : u;
        u = __shfl_sync(0xffffffff, P[j][2], src2);
        v = __shfl_sync(0xffffffff, P[j][3], src2);
        a3f = (q4 & 1) ? v : u;
        uint32_t Au[4] = {__float_as_uint(to_tf32(a0f)), __float_as_uint(to_tf32(a1f)),
                          __float_as_uint(to_tf32(a2f)), __float_as_uint(to_tf32(a3f))};
        uint32_t vp = smb + AT_V + (ks >> 2) * 8192;
        int kb2 = (ks & 3) * 32 + b_k16;
        uint32_t B0, B1, B2, B3;
#pragma unroll
        for (int p = 0; p < 4; p++) {
            int d = p * 16 + b_row;
            ldsm4(B0, B1, B2, B3, vp + d * 128 + (kb2 ^ ((d & 7) * 16)));
            uint32_t bf0[2] = {B0, B1}, bf1[2] = {B2, B3};
            mma8(O8[2 * p], Au, bf0);
            mma8(O8[2 * p + 1], Au, bf1);
        }
    }

    // ---- Epilogue: normalize, round to tf32 (feeds Wo GEMM), store ----
#pragma unroll
    for (int na = 0; na < 8; na++) {
        int gcol = colh + 8 * na + 2 * q4;
        float* o0 = O + (size_t)(row0 + r_lo) * D_MODEL + gcol;
        float* o1 = O + (size_t)(row0 + r_hi) * D_MODEL + gcol;
        *(float2*)o0 = make_float2(to_tf32(O8[na][0] * inv_lo), to_tf32(O8[na][1] * inv_lo));
        *(float2*)o1 = make_float2(to_tf32(O8[na][2] * inv_hi), to_tf32(O8[na][3] * inv_hi));
    }
}

// ---------------------------------------------------------------------------
extern "C" void kernel_launch(void* const* d_in, const int* in_sizes, int n_in,
                              void* d_out, int out_size) {
    const float* x  = (const float*)d_in[0];
    const float* Wq = (const float*)d_in[1];
    const float* Wk = (const float*)d_in[2];
    const float* Wv = (const float*)d_in[3];
    const float* Wo = (const float*)d_in[4];

    float *Qp, *Kp, *Vp, *Ap, *Xr, *Wqr, *Wkr, *Wvr, *Wor;
    cudaGetSymbolAddress((void**)&Qp,  g_Q);
    cudaGetSymbolAddress((void**)&Kp,  g_K);
    cudaGetSymbolAddress((void**)&Vp,  g_V);
    cudaGetSymbolAddress((void**)&Ap,  g_A);
    cudaGetSymbolAddress((void**)&Xr,  g_Xr);
    cudaGetSymbolAddress((void**)&Wqr, g_Wq);
    cudaGetSymbolAddress((void**)&Wkr, g_Wk);
    cudaGetSymbolAddress((void**)&Wvr, g_Wv);
    cudaGetSymbolAddress((void**)&Wor, g_Wo);

    cudaFuncSetAttribute(gemm_qkv,  cudaFuncAttributeMaxDynamicSharedMemorySize, GEMM_SMEM);
    cudaFuncSetAttribute(gemm_tf32, cudaFuncAttributeMaxDynamicSharedMemorySize, GEMM_SMEM);
    cudaFuncSetAttribute(swa_attn_tc, cudaFuncAttributeMaxDynamicSharedMemorySize, AT_SMEM);

    round_all_kernel<<<NTOT4 / 256, 256>>>(
        (const float4*)x, (const float4*)Wq, (const float4*)Wk,
        (const float4*)Wv, (const float4*)Wo,
        (float4*)Xr, (float4*)Wqr, (float4*)Wkr, (float4*)Wvr, (float4*)Wor);

    gemm_qkv<<<dim3(48, M_ROWS / 128), 256, GEMM_SMEM>>>(Xr, Wqr, Wkr, Wvr, Qp, Kp, Vp);

    swa_attn_tc<<<dim3(NBLK, N_HEADS, BATCH), 256, AT_SMEM>>>(Qp, Kp, Vp, Ap);

    gemm_tf32<<<dim3(16, M_ROWS / 128), 256, GEMM_SMEM>>>(Ap, Wor, (float*)d_out);
}

// round 15
// speedup vs baseline: 2.1439x; 1.7019x over previous
#include <cuda_runtime.h>
#include <cuda_fp16.h>
#include <cstdint>

// Problem constants.
#define T_SEQ   4096
#define D_MODEL 2048
#define N_HEADS 32
#define D_HEAD  64
#define BATCH   2
#define M_ROWS  (BATCH * T_SEQ)   // 8192
#define NBLK    (T_SEQ / 128)     // 32

// Scratch (device globals: allocation-free rule).
__device__ float  g_Q [M_ROWS * D_MODEL];
__device__ float  g_K [M_ROWS * D_MODEL];
__device__ float  g_V [M_ROWS * D_MODEL];
__device__ __half g_Ah[M_ROWS * D_MODEL];
__device__ __half g_Xh[M_ROWS * D_MODEL];
__device__ __half g_Wqh[D_MODEL * D_MODEL];
__device__ __half g_Wkh[D_MODEL * D_MODEL];
__device__ __half g_Wvh[D_MODEL * D_MODEL];
__device__ __half g_Woh[D_MODEL * D_MODEL];

// ---------------------------------------------------------------------------
// Helpers
// ---------------------------------------------------------------------------
__device__ __forceinline__ uint32_t smem_u32(const void* p) {
    uint32_t a;
    asm("{ .reg .u64 t; cvta.to.shared.u64 t, %1; cvt.u32.u64 %0, t; }" : "=r"(a) : "l"(p));
    return a;
}
__device__ __forceinline__ void cp16(uint32_t s, const void* g) {
    asm volatile("cp.async.cg.shared.global [%0], [%1], 16;" :: "r"(s), "l"(g));
}
__device__ __forceinline__ float to_tf32(float x) {
    uint32_t u;
    asm("cvt.rna.tf32.f32 %0, %1;" : "=r"(u) : "f"(x));
    return __uint_as_float(u);
}
#define SW128(b) ((b) ^ (((b) >> 3) & 0x70))

__device__ __forceinline__ void ldsm4(uint32_t& a, uint32_t& b, uint32_t& c,
                                      uint32_t& d, uint32_t addr) {
    asm volatile("ldmatrix.sync.aligned.m8n8.x4.shared.b16 {%0,%1,%2,%3}, [%4];"
                 : "=r"(a), "=r"(b), "=r"(c), "=r"(d) : "r"(addr));
}
// tf32 m16n8k8 (attention)
__device__ __forceinline__ void mma8(float* c, const uint32_t* a, const uint32_t* b) {
    asm volatile("mma.sync.aligned.m16n8k8.row.col.f32.tf32.tf32.f32 "
                 "{%0,%1,%2,%3},{%4,%5,%6,%7},{%8,%9},{%0,%1,%2,%3};"
                 : "+f"(c[0]), "+f"(c[1]), "+f"(c[2]), "+f"(c[3])
                 : "r"(a[0]), "r"(a[1]), "r"(a[2]), "r"(a[3]),
                   "r"(b[0]), "r"(b[1]));
}
// fp16 m16n8k16 (GEMMs)
__device__ __forceinline__ void mma16(float* c, const uint32_t* a, const uint32_t* b) {
    asm volatile("mma.sync.aligned.m16n8k16.row.col.f32.f16.f16.f32 "
                 "{%0,%1,%2,%3},{%4,%5,%6,%7},{%8,%9},{%0,%1,%2,%3};"
                 : "+f"(c[0]), "+f"(c[1]), "+f"(c[2]), "+f"(c[3])
                 : "r"(a[0]), "r"(a[1]), "r"(a[2]), "r"(a[3]),
                   "r"(b[0]), "r"(b[1]));
}

// ---------------------------------------------------------------------------
// Prep: convert [X | Wq | Wk | Wv | Wo] fp32 -> fp16 in ONE launch.
// ---------------------------------------------------------------------------
#define NX4 (M_ROWS * D_MODEL / 4)
#define NW4 (D_MODEL * D_MODEL / 4)
#define NTOT4 (NX4 + 4 * NW4)

__global__ void half_all_kernel(const float4* __restrict__ x,
                                const float4* __restrict__ wq,
                                const float4* __restrict__ wk,
                                const float4* __restrict__ wv,
                                const float4* __restrict__ wo,
                                __half2* __restrict__ xh,
                                __half2* __restrict__ wqh,
                                __half2* __restrict__ wkh,
                                __half2* __restrict__ wvh,
                                __half2* __restrict__ woh) {
    int i = blockIdx.x * blockDim.x + threadIdx.x;
    const float4* s;
    __half2* d;
    int off;
    if (i < NX4)                 { s = x;  d = xh;  off = i; }
    else if (i < NX4 + NW4)      { s = wq; d = wqh; off = i - NX4; }
    else if (i < NX4 + 2 * NW4)  { s = wk; d = wkh; off = i - NX4 - NW4; }
    else if (i < NX4 + 3 * NW4)  { s = wv; d = wvh; off = i - NX4 - 2 * NW4; }
    else                         { s = wo; d = woh; off = i - NX4 - 3 * NW4; }
    float4 v = s[off];
    d[off * 2]     = __floats2half2_rn(v.x, v.y);
    d[off * 2 + 1] = __floats2half2_rn(v.z, v.w);
}

// ---------------------------------------------------------------------------
// fp16 GEMM: C[m,n] = sum_k A[m,k]*B[n,k] (A MxK, B NxK row-major, __half).
// Tile 128x128, BK=64 halves (128B rows, same byte layout as tf32 version),
// 8 warps (2x4), 3-stage cp.async, 2 CTA/SM. NCHUNK = 32 (half of tf32).
// ---------------------------------------------------------------------------
#define BKH 64
#define STAGE_BYTES 32768
#define GEMM_SMEM (3 * STAGE_BYTES)

__device__ __forceinline__ void gemm_load_chunk(uint32_t smb, int kc,
                                                const __half* ag, const __half* bg,
                                                uint32_t soff) {
    uint32_t ab = smb + (uint32_t)(kc % 3) * STAGE_BYTES;
    uint32_t bb = ab + 16384;
    const __half* agp = ag + kc * BKH;
    const __half* bgp = bg + kc * BKH;
#pragma unroll
    for (int i = 0; i < 4; i++) {
        cp16(ab + soff + i * 4096, agp + (size_t)i * 32 * D_MODEL);
        cp16(bb + soff + i * 4096, bgp + (size_t)i * 32 * D_MODEL);
    }
    asm volatile("cp.async.commit_group;" ::: "memory");
}

__device__ __forceinline__ void gemm_body(const __half* __restrict__ A,
                                          const __half* __restrict__ B,
                                          float* __restrict__ C,
                                          int bm, int bn) {
    extern __shared__ __align__(1024) char sm[];
    uint32_t smb = smem_u32(sm);
    const int tid = threadIdx.x;
    const int wid = tid >> 5, lane = tid & 31;
    const int wm = wid & 1;
    const int wn = wid >> 1;

    // Loader: 4 A rows + 4 B rows (16B each) per chunk; row = 64 halves = 128B.
    const int r0 = tid >> 3;
    const int c4 = tid & 7;
    const __half* ag = A + (size_t)(bm + r0) * D_MODEL + c4 * 8;
    const __half* bg = B + (size_t)(bn + r0) * D_MODEL + c4 * 8;
    const uint32_t soff = SW128((uint32_t)(r0 * 128 + c4 * 16));

    const int lg = lane >> 3, lr = lane & 7;
    const int a_row = (lg & 1) * 8 + lr;
    const int a_k16 = (lg >> 1) * 16;
    const int b_row = (lg >> 1) * 8 + lr;
    const int b_k16 = (lg & 1) * 16;

    float  Cacc[4][4][4];
    uint32_t Af[4][4], Bf[4][2];
#pragma unroll
    for (int i = 0; i < 4; i++)
#pragma unroll
        for (int j = 0; j < 4; j++)
#pragma unroll
            for (int q = 0; q < 4; q++) Cacc[i][j][q] = 0.f;

    gemm_load_chunk(smb, 0, ag, bg, soff);
    gemm_load_chunk(smb, 1, ag, bg, soff);

    const int NCHUNK = D_MODEL / BKH;  // 32
    for (int c = 0; c < NCHUNK; c++) {
        if (c == NCHUNK - 1)
            asm volatile("cp.async.wait_group 0;" ::: "memory");
        else
            asm volatile("cp.async.wait_group 1;" ::: "memory");
        __syncthreads();
        if (c + 2 < NCHUNK) gemm_load_chunk(smb, c + 2, ag, bg, soff);

        uint32_t sa = smb + (uint32_t)(c % 3) * STAGE_BYTES;
        uint32_t sb = sa + 16384;
#pragma unroll
        for (int ks = 0; ks < 4; ks++) {       // K=16 halves (32 bytes) per step
            const int kb = ks * 32;
#pragma unroll
            for (int ma = 0; ma < 4; ma++) {
                int row = wm * 64 + ma * 16 + a_row;
                uint32_t off = (uint32_t)(row * 128 + ((row & 7) * 16 ^ (kb + a_k16)));
                ldsm4(Af[ma][0], Af[ma][1], Af[ma][2], Af[ma][3], sa + off);
            }
#pragma unroll
            for (int p = 0; p < 2; p++) {
                int n = wn * 32 + p * 16 + b_row;
                uint32_t off = (uint32_t)(n * 128 + ((n & 7) * 16 ^ (kb + b_k16)));
                ldsm4(Bf[p * 2][0], Bf[p * 2][1], Bf[p * 2 + 1][0], Bf[p * 2 + 1][1],
                      sb + off);
            }
#pragma unroll
            for (int ma = 0; ma < 4; ma++)
#pragma unroll
                for (int na = 0; na < 4; na++)
                    mma16(Cacc[ma][na], Af[ma], Bf[na]);
        }
    }

    const int er = lane >> 2, ec = (lane & 3) * 2;
#pragma unroll
    for (int ma = 0; ma < 4; ma++) {
        int grow = bm + wm * 64 + ma * 16 + er;
#pragma unroll
        for (int na = 0; na < 4; na++) {
            int gcol = bn + wn * 32 + na * 8 + ec;
            float* cp0 = C + (size_t)grow * D_MODEL + gcol;
            float* cp1 = C + (size_t)(grow + 8) * D_MODEL + gcol;
            *(float2*)cp0 = make_float2(Cacc[ma][na][0], Cacc[ma][na][1]);
            *(float2*)cp1 = make_float2(Cacc[ma][na][2], Cacc[ma][na][3]);
        }
    }
}

__global__ __launch_bounds__(256, 2) void gemm_qkv(const __half* __restrict__ A,
                                                   const __half* __restrict__ Bq,
                                                   const __half* __restrict__ Bk,
                                                   const __half* __restrict__ Bv,
                                                   float* __restrict__ Cq,
                                                   float* __restrict__ Ck,
                                                   float* __restrict__ Cv) {
    const int sel = blockIdx.x >> 4;
    const int bn = (blockIdx.x & 15) * 128;
    const int bm = blockIdx.y * 128;
    const __half* B = (sel == 0) ? Bq : (sel == 1) ? Bk : Bv;
    float* C = (sel == 0) ? Cq : (sel == 1) ? Ck : Cv;
    gemm_body(A, B, C, bm, bn);
}

__global__ __launch_bounds__(256, 2) void gemm_h16(const __half* __restrict__ A,
                                                   const __half* __restrict__ B,
                                                   float* __restrict__ C) {
    gemm_body(A, B, C, blockIdx.y * 128, blockIdx.x * 128);
}

// ---------------------------------------------------------------------------
// Tensor-core fused sliding-window attention (R14 band-skip version).
// Epilogue now writes __half (feeds fp16 Wo GEMM).
// ---------------------------------------------------------------------------
#define AT_Q 0
#define AT_K 32768
#define AT_V 98304
#define AT_SMEM 163840
#define NPA 18

__global__ __launch_bounds__(256, 1) void swa_attn_tc(const float* __restrict__ Q,
                                                      const float* __restrict__ Kmat,
                                                      const float* __restrict__ V,
                                                      __half* __restrict__ Oh) {
    extern __shared__ __align__(1024) char sm[];
    uint32_t smb = smem_u32(sm);
    float* smf = (float*)sm;

    const int tid  = threadIdx.x;
    const int wid  = tid >> 5, lane = tid & 31;
    const int iblk = blockIdx.x;
    const int h    = blockIdx.y;
    const int b    = blockIdx.z;
    const int row0 = b * T_SEQ + iblk * 128;
    const int colh = h * D_HEAD;
    const int bbase = b * T_SEQ;

    for (int idx = tid; idx < 128 * 16; idx += 256) {
        int r = idx >> 4, d4 = idx & 15;
        int panel = d4 >> 3, x = (d4 & 7) * 16;
        cp16(smb + AT_Q + panel * 16384 + r * 128 + (x ^ ((r & 7) * 16)),
             Q + (size_t)(row0 + r) * D_MODEL + colh + d4 * 4);
    }
    asm volatile("cp.async.commit_group;" ::: "memory");

    {
        int krow = row0 - 128 + tid;
        if (krow < bbase) krow = bbase;
        const float* kg = Kmat + (size_t)krow * D_MODEL + colh;
        uint32_t kbase = smb + AT_K + tid * 128;
#pragma unroll
        for (int d4 = 0; d4 < 16; d4++) {
            float4 v = *(const float4*)(kg + d4 * 4);
            v.x = to_tf32(v.x); v.y = to_tf32(v.y);
            v.z = to_tf32(v.z); v.w = to_tf32(v.w);
            int panel = d4 >> 3, x = (d4 & 7) * 16;
            *(float4*)(sm + (kbase - smb) + panel * 32768 + (x ^ ((tid & 7) * 16))) = v;
        }
    }
    {
        int krow = row0 - 128 + tid;
        if (krow < bbase) krow = bbase;
        const float* vg = V + (size_t)krow * D_MODEL + colh;
        const int kp = tid >> 5;
        const int kx = (tid & 31) * 4;
        const int vbase = (AT_V >> 2) + kp * 2048;
#pragma unroll
        for (int d4 = 0; d4 < 16; d4++) {
            float4 v = *(const float4*)(vg + d4 * 4);
            int d = d4 * 4;
            smf[vbase + (d + 0) * 32 + (((uint32_t)kx ^ (((d + 0) & 7) * 16)) >> 2)] = to_tf32(v.x);
            smf[vbase + (d + 1) * 32 + (((uint32_t)kx ^ (((d + 1) & 7) * 16)) >> 2)] = to_tf32(v.y);
            smf[vbase + (d + 2) * 32 + (((uint32_t)kx ^ (((d + 2) & 7) * 16)) >> 2)] = to_tf32(v.z);
            smf[vbase + (d + 3) * 32 + (((uint32_t)kx ^ (((d + 3) & 7) * 16)) >> 2)] = to_tf32(v.w);
        }
    }
    asm volatile("cp.async.wait_group 0;" ::: "memory");
    __syncthreads();

    const int lg = lane >> 3, lr = lane & 7;
    const int a_row = (lg & 1) * 8 + lr;
    const int a_k16 = (lg >> 1) * 16;
    const int b_row = (lg >> 1) * 8 + lr;
    const int b_k16 = (lg & 1) * 16;
    const int q4 = lane & 3;

    float P[NPA][4];
#pragma unroll
    for (int i = 0; i < NPA; i++)
#pragma unroll
        for (int j = 0; j < 4; j++) P[i][j] = 0.f;

    {
        const int arow_g = wid * 16 + a_row;
        uint32_t Ar[4], Ahi[4], Alo[4], B0, B1, B2, B3;
#pragma unroll
        for (int ks = 0; ks < 8; ks++) {
            int kbyte = ks * 32 + a_k16;
            ldsm4(Ar[0], Ar[1], Ar[2], Ar[3],
                  smb + AT_Q + (kbyte >> 7) * 16384 + arow_g * 128 +
                  ((kbyte & 127) ^ ((arow_g & 7) * 16)));
#pragma unroll
            for (int i = 0; i < 4; i++) {
                float x = __uint_as_float(Ar[i]);
                float hi = to_tf32(x);
                Ahi[i] = __float_as_uint(hi);
                Alo[i] = __float_as_uint(to_tf32(x - hi));
            }
            int kbb = ks * 32 + b_k16;
            uint32_t pb = smb + AT_K + (kbb >> 7) * 32768;
            int xb = kbb & 127;
#pragma unroll
            for (int dnp = 0; dnp < 9; dnp++) {
                int c = (wid + dnp) * 16 + b_row;
                ldsm4(B0, B1, B2, B3, pb + c * 128 + (xb ^ ((c & 7) * 16)));
                uint32_t bf0[2] = {B0, B1}, bf1[2] = {B2, B3};
                mma8(P[2 * dnp], Ahi, bf0);
                mma8(P[2 * dnp], Alo, bf0);
                mma8(P[2 * dnp + 1], Ahi, bf1);
                mma8(P[2 * dnp + 1], Alo, bf1);
            }
        }
    }

    const int r_lo = wid * 16 + (lane >> 2);
    const int r_hi = r_lo + 8;
    const float scale = 0.125f;
    float m_lo = -1e30f, m_hi = -1e30f;
#pragma unroll
    for (int j = 0; j < NPA; j++) {
        int c0 = 8 * (2 * wid + j) + 2 * q4, c1 = c0 + 1;
        bool ok0 = (iblk > 0 || c0 >= 128);
        bool ok1 = (iblk > 0 || c1 >= 128);
        float s0 = (ok0 && c0 >= r_lo && c0 <= r_lo + 128) ? P[j][0] * scale : -1e30f;
        float s1 = (ok1 && c1 >= r_lo && c1 <= r_lo + 128) ? P[j][1] * scale : -1e30f;
        float s2 = (ok0 && c0 >= r_hi && c0 <= r_hi + 128) ? P[j][2] * scale : -1e30f;
        float s3 = (ok1 && c1 >= r_hi && c1 <= r_hi + 128) ? P[j][3] * scale : -1e30f;
        P[j][0] = s0; P[j][1] = s1; P[j][2] = s2; P[j][3] = s3;
        m_lo = fmaxf(m_lo, fmaxf(s0, s1));
        m_hi = fmaxf(m_hi, fmaxf(s2, s3));
    }
    m_lo = fmaxf(m_lo, __shfl_xor_sync(0xffffffff, m_lo, 1));
    m_lo = fmaxf(m_lo, __shfl_xor_sync(0xffffffff, m_lo, 2));
    m_hi = fmaxf(m_hi, __shfl_xor_sync(0xffffffff, m_hi, 1));
    m_hi = fmaxf(m_hi, __shfl_xor_sync(0xffffffff, m_hi, 2));
    float s_lo = 0.f, s_hi = 0.f;
#pragma unroll
    for (int j = 0; j < NPA; j++) {
        float e0 = __expf(P[j][0] - m_lo);
        float e1 = __expf(P[j][1] - m_lo);
        float e2 = __expf(P[j][2] - m_hi);
        float e3 = __expf(P[j][3] - m_hi);
        P[j][0] = e0; P[j][1] = e1; P[j][2] = e2; P[j][3] = e3;
        s_lo += e0 + e1; s_hi += e2 + e3;
    }
    s_lo += __shfl_xor_sync(0xffffffff, s_lo, 1);
    s_lo += __shfl_xor_sync(0xffffffff, s_lo, 2);
    s_hi += __shfl_xor_sync(0xffffffff, s_hi, 1);
    s_hi += __shfl_xor_sync(0xffffffff, s_hi, 2);
    const float inv_lo = 1.f / s_lo, inv_hi = 1.f / s_hi;

    float O8[8][4];
#pragma unroll
    for (int i = 0; i < 8; i++)
#pragma unroll
        for (int j = 0; j < 4; j++) O8[i][j] = 0.f;

    const int src1 = (lane & ~3) | (q4 >> 1);
    const int src2 = src1 + 2;
#pragma unroll
    for (int j = 0; j < NPA; j++) {
        const int ks = 2 * wid + j;
        float u, v, a0f, a1f, a2f, a3f;
        u = __shfl_sync(0xffffffff, P[j][0], src1);
        v = __shfl_sync(0xffffffff, P[j][1], src1);
        a0f = (q4 & 1) ? v : u;
        u = __shfl_sync(0xffffffff, P[j][2], src1);
        v = __shfl_sync(0xffffffff, P[j][3], src1);
        a1f = (q4 & 1) ? v : u;
        u = __shfl_sync(0xffffffff, P[j][0], src2);
        v = __shfl_sync(0xffffffff, P[j][1], src2);
        a2f = (q4 & 1) ? v : u;
        u = __shfl_sync(0xffffffff, P[j][2], src2);
        v = __shfl_sync(0xffffffff, P[j][3], src2);
        a3f = (q4 & 1) ? v : u;
        uint32_t Au[4] = {__float_as_uint(to_tf32(a0f)), __float_as_uint(to_tf32(a1f)),
                          __float_as_uint(to_tf32(a2f)), __float_as_uint(to_tf32(a3f))};
        uint32_t vp = smb + AT_V + (ks >> 2) * 8192;
        int kb2 = (ks & 3) * 32 + b_k16;
        uint32_t B0, B1, B2, B3;
#pragma unroll
        for (int p = 0; p < 4; p++) {
            int d = p * 16 + b_row;
            ldsm4(B0, B1, B2, B3, vp + d * 128 + (kb2 ^ ((d & 7) * 16)));
            uint32_t bf0[2] = {B0, B1}, bf1[2] = {B2, B3};
            mma8(O8[2 * p], Au, bf0);
            mma8(O8[2 * p + 1], Au, bf1);
        }
    }

    // ---- Epilogue: normalize, convert to fp16 (feeds fp16 Wo GEMM) ----
#pragma unroll
    for (int na = 0; na < 8; na++) {
        int gcol = colh + 8 * na + 2 * q4;
        __half2* o0 = (__half2*)(Oh + (size_t)(row0 + r_lo) * D_MODEL + gcol);
        __half2* o1 = (__half2*)(Oh + (size_t)(row0 + r_hi) * D_MODEL + gcol);
        *o0 = __floats2half2_rn(O8[na][0] * inv_lo, O8[na][1] * inv_lo);
        *o1 = __floats2half2_rn(O8[na][2] * inv_hi, O8[na][3] * inv_hi);
    }
}

// ---------------------------------------------------------------------------
extern "C" void kernel_launch(void* const* d_in, const int* in_sizes, int n_in,
                              void* d_out, int out_size) {
    const float* x  = (const float*)d_in[0];
    const float* Wq = (const float*)d_in[1];
    const float* Wk = (const float*)d_in[2];
    const float* Wv = (const float*)d_in[3];
    const float* Wo = (const float*)d_in[4];

    float *Qp, *Kp, *Vp;
    __half *Ah, *Xh, *Wqh, *Wkh, *Wvh, *Woh;
    cudaGetSymbolAddress((void**)&Qp,  g_Q);
    cudaGetSymbolAddress((void**)&Kp,  g_K);
    cudaGetSymbolAddress((void**)&Vp,  g_V);
    cudaGetSymbolAddress((void**)&Ah,  g_Ah);
    cudaGetSymbolAddress((void**)&Xh,  g_Xh);
    cudaGetSymbolAddress((void**)&Wqh, g_Wqh);
    cudaGetSymbolAddress((void**)&Wkh, g_Wkh);
    cudaGetSymbolAddress((void**)&Wvh, g_Wvh);
    cudaGetSymbolAddress((void**)&Woh, g_Woh);

    cudaFuncSetAttribute(gemm_qkv, cudaFuncAttributeMaxDynamicSharedMemorySize, GEMM_SMEM);
    cudaFuncSetAttribute(gemm_h16, cudaFuncAttributeMaxDynamicSharedMemorySize, GEMM_SMEM);
    cudaFuncSetAttribute(swa_attn_tc, cudaFuncAttributeMaxDynamicSharedMemorySize, AT_SMEM);

    half_all_kernel<<<NTOT4 / 256, 256>>>(
        (const float4*)x, (const float4*)Wq, (const float4*)Wk,
        (const float4*)Wv, (const float4*)Wo,
        (__half2*)Xh, (__half2*)Wqh, (__half2*)Wkh, (__half2*)Wvh, (__half2*)Woh);

    gemm_qkv<<<dim3(48, M_ROWS / 128), 256, GEMM_SMEM>>>(Xh, Wqh, Wkh, Wvh, Qp, Kp, Vp);

    swa_attn_tc<<<dim3(NBLK, N_HEADS, BATCH), 256, AT_SMEM>>>(Qp, Kp, Vp, Ah);

    gemm_h16<<<dim3(16, M_ROWS / 128), 256, GEMM_SMEM>>>(Ah, Woh, (float*)d_out);
}

// round 16
// speedup vs baseline: 2.4774x; 1.1555x over previous
#include <cuda_runtime.h>
#include <cuda_fp16.h>
#include <cstdint>

// Problem constants.
#define T_SEQ   4096
#define D_MODEL 2048
#define N_HEADS 32
#define D_HEAD  64
#define BATCH   2
#define M_ROWS  (BATCH * T_SEQ)   // 8192
#define NBLK    (T_SEQ / 128)     // 32

// Scratch (device globals: allocation-free rule).
__device__ __half g_Qh[M_ROWS * D_MODEL];
__device__ __half g_Kh[M_ROWS * D_MODEL];
__device__ __half g_Vh[M_ROWS * D_MODEL];
__device__ __half g_Ah[M_ROWS * D_MODEL];
__device__ __half g_Xh[M_ROWS * D_MODEL];
__device__ __half g_Wqh[D_MODEL * D_MODEL];
__device__ __half g_Wkh[D_MODEL * D_MODEL];
__device__ __half g_Wvh[D_MODEL * D_MODEL];
__device__ __half g_Woh[D_MODEL * D_MODEL];

// ---------------------------------------------------------------------------
// Helpers
// ---------------------------------------------------------------------------
__device__ __forceinline__ uint32_t smem_u32(const void* p) {
    uint32_t a;
    asm("{ .reg .u64 t; cvta.to.shared.u64 t, %1; cvt.u32.u64 %0, t; }" : "=r"(a) : "l"(p));
    return a;
}
__device__ __forceinline__ void cp16(uint32_t s, const void* g) {
    asm volatile("cp.async.cg.shared.global [%0], [%1], 16;" :: "r"(s), "l"(g));
}
#define SW128(b) ((b) ^ (((b) >> 3) & 0x70))

__device__ __forceinline__ void ldsm4(uint32_t& a, uint32_t& b, uint32_t& c,
                                      uint32_t& d, uint32_t addr) {
    asm volatile("ldmatrix.sync.aligned.m8n8.x4.shared.b16 {%0,%1,%2,%3}, [%4];"
                 : "=r"(a), "=r"(b), "=r"(c), "=r"(d) : "r"(addr));
}
__device__ __forceinline__ void mma16(float* c, const uint32_t* a, const uint32_t* b) {
    asm volatile("mma.sync.aligned.m16n8k16.row.col.f32.f16.f16.f32 "
                 "{%0,%1,%2,%3},{%4,%5,%6,%7},{%8,%9},{%0,%1,%2,%3};"
                 : "+f"(c[0]), "+f"(c[1]), "+f"(c[2]), "+f"(c[3])
                 : "r"(a[0]), "r"(a[1]), "r"(a[2]), "r"(a[3]),
                   "r"(b[0]), "r"(b[1]));
}
__device__ __forceinline__ uint32_t packh2(float lo, float hi) {
    __half2 h = __floats2half2_rn(lo, hi);
    return *(uint32_t*)&h;
}

// ---------------------------------------------------------------------------
// Prep: convert [X | Wq | Wk | Wv | Wo] fp32 -> fp16 in ONE launch.
// ---------------------------------------------------------------------------
#define NX4 (M_ROWS * D_MODEL / 4)
#define NW4 (D_MODEL * D_MODEL / 4)
#define NTOT4 (NX4 + 4 * NW4)

__global__ void half_all_kernel(const float4* __restrict__ x,
                                const float4* __restrict__ wq,
                                const float4* __restrict__ wk,
                                const float4* __restrict__ wv,
                                const float4* __restrict__ wo,
                                __half2* __restrict__ xh,
                                __half2* __restrict__ wqh,
                                __half2* __restrict__ wkh,
                                __half2* __restrict__ wvh,
                                __half2* __restrict__ woh) {
    int i = blockIdx.x * blockDim.x + threadIdx.x;
    const float4* s;
    __half2* d;
    int off;
    if (i < NX4)                 { s = x;  d = xh;  off = i; }
    else if (i < NX4 + NW4)      { s = wq; d = wqh; off = i - NX4; }
    else if (i < NX4 + 2 * NW4)  { s = wk; d = wkh; off = i - NX4 - NW4; }
    else if (i < NX4 + 3 * NW4)  { s = wv; d = wvh; off = i - NX4 - 2 * NW4; }
    else                         { s = wo; d = woh; off = i - NX4 - 3 * NW4; }
    float4 v = s[off];
    d[off * 2]     = __floats2half2_rn(v.x, v.y);
    d[off * 2 + 1] = __floats2half2_rn(v.z, v.w);
}

// ---------------------------------------------------------------------------
// fp16 GEMM (R15 config): tile 128x128, BK=64 halves, 8 warps, 3-stage, 2 CTA/SM.
// HALF_OUT selects fp16 (QKV, feeds attention) vs fp32 (Wo, final output).
// ---------------------------------------------------------------------------
#define BKH 64
#define STAGE_BYTES 32768
#define GEMM_SMEM (3 * STAGE_BYTES)

__device__ __forceinline__ void gemm_load_chunk(uint32_t smb, int kc,
                                                const __half* ag, const __half* bg,
                                                uint32_t soff) {
    uint32_t ab = smb + (uint32_t)(kc % 3) * STAGE_BYTES;
    uint32_t bb = ab + 16384;
    const __half* agp = ag + kc * BKH;
    const __half* bgp = bg + kc * BKH;
#pragma unroll
    for (int i = 0; i < 4; i++) {
        cp16(ab + soff + i * 4096, agp + (size_t)i * 32 * D_MODEL);
        cp16(bb + soff + i * 4096, bgp + (size_t)i * 32 * D_MODEL);
    }
    asm volatile("cp.async.commit_group;" ::: "memory");
}

template <bool HALF_OUT>
__device__ __forceinline__ void gemm_body(const __half* __restrict__ A,
                                          const __half* __restrict__ B,
                                          void* __restrict__ C,
                                          int bm, int bn) {
    extern __shared__ __align__(1024) char sm[];
    uint32_t smb = smem_u32(sm);
    const int tid = threadIdx.x;
    const int wid = tid >> 5, lane = tid & 31;
    const int wm = wid & 1;
    const int wn = wid >> 1;

    const int r0 = tid >> 3;
    const int c4 = tid & 7;
    const __half* ag = A + (size_t)(bm + r0) * D_MODEL + c4 * 8;
    const __half* bg = B + (size_t)(bn + r0) * D_MODEL + c4 * 8;
    const uint32_t soff = SW128((uint32_t)(r0 * 128 + c4 * 16));

    const int lg = lane >> 3, lr = lane & 7;
    const int a_row = (lg & 1) * 8 + lr;
    const int a_k16 = (lg >> 1) * 16;
    const int b_row = (lg >> 1) * 8 + lr;
    const int b_k16 = (lg & 1) * 16;

    float  Cacc[4][4][4];
    uint32_t Af[4][4], Bf[4][2];
#pragma unroll
    for (int i = 0; i < 4; i++)
#pragma unroll
        for (int j = 0; j < 4; j++)
#pragma unroll
            for (int q = 0; q < 4; q++) Cacc[i][j][q] = 0.f;

    gemm_load_chunk(smb, 0, ag, bg, soff);
    gemm_load_chunk(smb, 1, ag, bg, soff);

    const int NCHUNK = D_MODEL / BKH;  // 32
    for (int c = 0; c < NCHUNK; c++) {
        if (c == NCHUNK - 1)
            asm volatile("cp.async.wait_group 0;" ::: "memory");
        else
            asm volatile("cp.async.wait_group 1;" ::: "memory");
        __syncthreads();
        if (c + 2 < NCHUNK) gemm_load_chunk(smb, c + 2, ag, bg, soff);

        uint32_t sa = smb + (uint32_t)(c % 3) * STAGE_BYTES;
        uint32_t sb = sa + 16384;
#pragma unroll
        for (int ks = 0; ks < 4; ks++) {
            const int kb = ks * 32;
#pragma unroll
            for (int ma = 0; ma < 4; ma++) {
                int row = wm * 64 + ma * 16 + a_row;
                uint32_t off = (uint32_t)(row * 128 + ((row & 7) * 16 ^ (kb + a_k16)));
                ldsm4(Af[ma][0], Af[ma][1], Af[ma][2], Af[ma][3], sa + off);
            }
#pragma unroll
            for (int p = 0; p < 2; p++) {
                int n = wn * 32 + p * 16 + b_row;
                uint32_t off = (uint32_t)(n * 128 + ((n & 7) * 16 ^ (kb + b_k16)));
                ldsm4(Bf[p * 2][0], Bf[p * 2][1], Bf[p * 2 + 1][0], Bf[p * 2 + 1][1],
                      sb + off);
            }
#pragma unroll
            for (int ma = 0; ma < 4; ma++)
#pragma unroll
                for (int na = 0; na < 4; na++)
                    mma16(Cacc[ma][na], Af[ma], Bf[na]);
        }
    }

    const int er = lane >> 2, ec = (lane & 3) * 2;
#pragma unroll
    for (int ma = 0; ma < 4; ma++) {
        int grow = bm + wm * 64 + ma * 16 + er;
#pragma unroll
        for (int na = 0; na < 4; na++) {
            int gcol = bn + wn * 32 + na * 8 + ec;
            if (HALF_OUT) {
                __half2* cp0 = (__half2*)((__half*)C + (size_t)grow * D_MODEL + gcol);
                __half2* cp1 = (__half2*)((__half*)C + (size_t)(grow + 8) * D_MODEL + gcol);
                *cp0 = __floats2half2_rn(Cacc[ma][na][0], Cacc[ma][na][1]);
                *cp1 = __floats2half2_rn(Cacc[ma][na][2], Cacc[ma][na][3]);
            } else {
                float* cp0 = (float*)C + (size_t)grow * D_MODEL + gcol;
                float* cp1 = (float*)C + (size_t)(grow + 8) * D_MODEL + gcol;
                *(float2*)cp0 = make_float2(Cacc[ma][na][0], Cacc[ma][na][1]);
                *(float2*)cp1 = make_float2(Cacc[ma][na][2], Cacc[ma][na][3]);
            }
        }
    }
}

__global__ __launch_bounds__(256, 2) void gemm_qkv(const __half* __restrict__ A,
                                                   const __half* __restrict__ Bq,
                                                   const __half* __restrict__ Bk,
                                                   const __half* __restrict__ Bv,
                                                   __half* __restrict__ Cq,
                                                   __half* __restrict__ Ck,
                                                   __half* __restrict__ Cv) {
    const int sel = blockIdx.x >> 4;
    const int bn = (blockIdx.x & 15) * 128;
    const int bm = blockIdx.y * 128;
    const __half* B = (sel == 0) ? Bq : (sel == 1) ? Bk : Bv;
    __half* C = (sel == 0) ? Cq : (sel == 1) ? Ck : Cv;
    gemm_body<true>(A, B, C, bm, bn);
}

__global__ __launch_bounds__(256, 2) void gemm_h16(const __half* __restrict__ A,
                                                   const __half* __restrict__ B,
                                                   float* __restrict__ C) {
    gemm_body<false>(A, B, C, blockIdx.y * 128, blockIdx.x * 128);
}

// ---------------------------------------------------------------------------
// fp16 fused sliding-window attention with band skip.
// Smem: Q [128][128B] fp16, K [256][128B] fp16, Vt 4 panels [64 d][128B]
// (keys 64/panel, key-major halves). 80KB -> 2 CTA/SM.
// QK: m16n8k16, 72 MMAs/warp. PV: P C-frag cols ARE the fp16 A k-pairs ->
// zero-shuffle repack. Masked/clamped keys contribute exact 0.
// ---------------------------------------------------------------------------
#define AT_Q 0
#define AT_K 16384
#define AT_V 49152
#define AT_SMEM 81920
#define NPA 18

__global__ __launch_bounds__(256, 2) void swa_attn_tc(const __half* __restrict__ Q,
                                                      const __half* __restrict__ Kmat,
                                                      const __half* __restrict__ V,
                                                      __half* __restrict__ Oh) {
    extern __shared__ __align__(1024) char sm[];
    uint32_t smb = smem_u32(sm);

    const int tid  = threadIdx.x;
    const int wid  = tid >> 5, lane = tid & 31;
    const int iblk = blockIdx.x;
    const int h    = blockIdx.y;
    const int b    = blockIdx.z;
    const int row0 = b * T_SEQ + iblk * 128;
    const int colh = h * D_HEAD;
    const int bbase = b * T_SEQ;

    // ---- Stage Q fp16 (cp.async, SW128): 128 rows x 8 x 16B ----
    for (int idx = tid; idx < 128 * 8; idx += 256) {
        int r = idx >> 3, c16 = idx & 7;
        cp16(smb + AT_Q + r * 128 + ((c16 * 16) ^ ((r & 7) * 16)),
             Q + (size_t)(row0 + r) * D_MODEL + colh + c16 * 8);
    }
    // ---- Stage K fp16 (cp.async): 256 rows (clamped) x 8 x 16B ----
    for (int idx = tid; idx < 256 * 8; idx += 256) {
        int c = idx >> 3, c16 = idx & 7;
        int krow = row0 - 128 + c;
        if (krow < bbase) krow = bbase;
        cp16(smb + AT_K + c * 128 + ((c16 * 16) ^ ((c & 7) * 16)),
             Kmat + (size_t)krow * D_MODEL + colh + c16 * 8);
    }
    asm volatile("cp.async.commit_group;" ::: "memory");

    // ---- Stage V transposed fp16: thread = (key pair pr, d-half dh) ----
    {
        const int pr = tid & 127;          // key pair index 0..127
        const int dh = (tid >> 7) * 32;    // d offset 0 or 32
        int k0 = row0 - 128 + 2 * pr;
        int k1 = k0 + 1;
        if (k0 < bbase) k0 = bbase;
        if (k1 < bbase) k1 = bbase;
        const uint32_t* v0 = (const uint32_t*)(V + (size_t)k0 * D_MODEL + colh + dh);
        const uint32_t* v1 = (const uint32_t*)(V + (size_t)k1 * D_MODEL + colh + dh);
        uint32_t r0v[16], r1v[16];
#pragma unroll
        for (int i = 0; i < 4; i++) {
            *(uint4*)&r0v[i * 4] = *(const uint4*)&v0[i * 4];
            *(uint4*)&r1v[i * 4] = *(const uint4*)&v1[i * 4];
        }
        uint32_t vb = smb + AT_V + (uint32_t)(pr >> 5) * 8192;
        uint32_t kob = (uint32_t)(pr & 31) * 4;
#pragma unroll
        for (int i = 0; i < 16; i++) {
            int d0 = dh + 2 * i, d1 = d0 + 1;
            uint32_t w0 = __byte_perm(r0v[i], r1v[i], 0x5410);
            uint32_t w1 = __byte_perm(r0v[i], r1v[i], 0x7632);
            *(uint32_t*)(sm + (vb - smb) + d0 * 128 + (kob ^ ((d0 & 7) * 16))) = w0;
            *(uint32_t*)(sm + (vb - smb) + d1 * 128 + (kob ^ ((d1 & 7) * 16))) = w1;
        }
    }
    asm volatile("cp.async.wait_group 0;" ::: "memory");
    __syncthreads();

    const int lg = lane >> 3, lr = lane & 7;
    const int a_row = (lg & 1) * 8 + lr;
    const int a_k16 = (lg >> 1) * 16;
    const int b_row = (lg >> 1) * 8 + lr;
    const int b_k16 = (lg & 1) * 16;
    const int q4 = lane & 3;

    // ---- QK^T fp16: P[j] = 8-key atom (2*wid + j), j in [0,18) ----
    float P[NPA][4];
#pragma unroll
    for (int i = 0; i < NPA; i++)
#pragma unroll
        for (int j = 0; j < 4; j++) P[i][j] = 0.f;

    {
        const int arow_g = wid * 16 + a_row;
        uint32_t Af[4], B0, B1, B2, B3;
#pragma unroll
        for (int ks = 0; ks < 4; ks++) {      // K = 16 halves (32B) per step
            int kb = ks * 32;
            ldsm4(Af[0], Af[1], Af[2], Af[3],
                  smb + AT_Q + arow_g * 128 + ((kb + a_k16) ^ ((arow_g & 7) * 16)));
#pragma unroll
            for (int dnp = 0; dnp < 9; dnp++) {
                int c = (wid + dnp) * 16 + b_row;
                ldsm4(B0, B1, B2, B3,
                      smb + AT_K + c * 128 + ((kb + b_k16) ^ ((c & 7) * 16)));
                uint32_t bf0[2] = {B0, B1}, bf1[2] = {B2, B3};
                mma16(P[2 * dnp], Af, bf0);
                mma16(P[2 * dnp + 1], Af, bf1);
            }
        }
    }

    // ---- Mask + softmax over the 18 band atoms ----
    const int r_lo = wid * 16 + (lane >> 2);
    const int r_hi = r_lo + 8;
    const float scale = 0.125f;
    float m_lo = -1e30f, m_hi = -1e30f;
#pragma unroll
    for (int j = 0; j < NPA; j++) {
        int c0 = 8 * (2 * wid + j) + 2 * q4, c1 = c0 + 1;
        bool ok0 = (iblk > 0 || c0 >= 128);
        bool ok1 = (iblk > 0 || c1 >= 128);
        float s0 = (ok0 && c0 >= r_lo && c0 <= r_lo + 128) ? P[j][0] * scale : -1e30f;
        float s1 = (ok1 && c1 >= r_lo && c1 <= r_lo + 128) ? P[j][1] * scale : -1e30f;
        float s2 = (ok0 && c0 >= r_hi && c0 <= r_hi + 128) ? P[j][2] * scale : -1e30f;
        float s3 = (ok1 && c1 >= r_hi && c1 <= r_hi + 128) ? P[j][3] * scale : -1e30f;
        P[j][0] = s0; P[j][1] = s1; P[j][2] = s2; P[j][3] = s3;
        m_lo = fmaxf(m_lo, fmaxf(s0, s1));
        m_hi = fmaxf(m_hi, fmaxf(s2, s3));
    }
    m_lo = fmaxf(m_lo, __shfl_xor_sync(0xffffffff, m_lo, 1));
    m_lo = fmaxf(m_lo, __shfl_xor_sync(0xffffffff, m_lo, 2));
    m_hi = fmaxf(m_hi, __shfl_xor_sync(0xffffffff, m_hi, 1));
    m_hi = fmaxf(m_hi, __shfl_xor_sync(0xffffffff, m_hi, 2));
    float s_lo = 0.f, s_hi = 0.f;
#pragma unroll
    for (int j = 0; j < NPA; j++) {
        float e0 = __expf(P[j][0] - m_lo);
        float e1 = __expf(P[j][1] - m_lo);
        float e2 = __expf(P[j][2] - m_hi);
        float e3 = __expf(P[j][3] - m_hi);
        P[j][0] = e0; P[j][1] = e1; P[j][2] = e2; P[j][3] = e3;
        s_lo += e0 + e1; s_hi += e2 + e3;
    }
    s_lo += __shfl_xor_sync(0xffffffff, s_lo, 1);
    s_lo += __shfl_xor_sync(0xffffffff, s_lo, 2);
    s_hi += __shfl_xor_sync(0xffffffff, s_hi, 1);
    s_hi += __shfl_xor_sync(0xffffffff, s_hi, 2);
    const float inv_lo = 1.f / s_lo, inv_hi = 1.f / s_hi;

    // ---- PV fp16: step s covers keys 16*(wid+s); A = packed P atoms 2s,2s+1 ----
    float O8[8][4];
#pragma unroll
    for (int i = 0; i < 8; i++)
#pragma unroll
        for (int j = 0; j < 4; j++) O8[i][j] = 0.f;

#pragma unroll
    for (int s = 0; s < 9; s++) {
        uint32_t Au[4];
        Au[0] = packh2(P[2 * s][0],     P[2 * s][1]);
        Au[1] = packh2(P[2 * s][2],     P[2 * s][3]);
        Au[2] = packh2(P[2 * s + 1][0], P[2 * s + 1][1]);
        Au[3] = packh2(P[2 * s + 1][2], P[2 * s + 1][3]);
        const int gk = wid + s;                  // 16-key step index
        uint32_t vp = smb + AT_V + (uint32_t)(gk >> 2) * 8192;
        int kb2 = (gk & 3) * 32;                 // key-byte base within panel
        uint32_t B0, B1, B2, B3;
#pragma unroll
        for (int p = 0; p < 4; p++) {
            int d = p * 16 + b_row;
            ldsm4(B0, B1, B2, B3, vp + d * 128 + ((kb2 + b_k16) ^ ((d & 7) * 16)));
            uint32_t bf0[2] = {B0, B1}, bf1[2] = {B2, B3};
            mma16(O8[2 * p], Au, bf0);
            mma16(O8[2 * p + 1], Au, bf1);
        }
    }

    // ---- Epilogue: normalize, fp16 out (feeds Wo GEMM) ----
#pragma unroll
    for (int na = 0; na < 8; na++) {
        int gcol = colh + 8 * na + 2 * q4;
        __half2* o0 = (__half2*)(Oh + (size_t)(row0 + r_lo) * D_MODEL + gcol);
        __half2* o1 = (__half2*)(Oh + (size_t)(row0 + r_hi) * D_MODEL + gcol);
        *o0 = __floats2half2_rn(O8[na][0] * inv_lo, O8[na][1] * inv_lo);
        *o1 = __floats2half2_rn(O8[na][2] * inv_hi, O8[na][3] * inv_hi);
    }
}

// ---------------------------------------------------------------------------
extern "C" void kernel_launch(void* const* d_in, const int* in_sizes, int n_in,
                              void* d_out, int out_size) {
    const float* x  = (const float*)d_in[0];
    const float* Wq = (const float*)d_in[1];
    const float* Wk = (const float*)d_in[2];
    const float* Wv = (const float*)d_in[3];
    const float* Wo = (const float*)d_in[4];

    __half *Qh, *Kh, *Vh, *Ah, *Xh, *Wqh, *Wkh, *Wvh, *Woh;
    cudaGetSymbolAddress((void**)&Qh,  g_Qh);
    cudaGetSymbolAddress((void**)&Kh,  g_Kh);
    cudaGetSymbolAddress((void**)&Vh,  g_Vh);
    cudaGetSymbolAddress((void**)&Ah,  g_Ah);
    cudaGetSymbolAddress((void**)&Xh,  g_Xh);
    cudaGetSymbolAddress((void**)&Wqh, g_Wqh);
    cudaGetSymbolAddress((void**)&Wkh, g_Wkh);
    cudaGetSymbolAddress((void**)&Wvh, g_Wvh);
    cudaGetSymbolAddress((void**)&Woh, g_Woh);

    cudaFuncSetAttribute(gemm_qkv, cudaFuncAttributeMaxDynamicSharedMemorySize, GEMM_SMEM);
    cudaFuncSetAttribute(gemm_h16, cudaFuncAttributeMaxDynamicSharedMemorySize, GEMM_SMEM);
    cudaFuncSetAttribute(swa_attn_tc, cudaFuncAttributeMaxDynamicSharedMemorySize, AT_SMEM);

    half_all_kernel<<<NTOT4 / 256, 256>>>(
        (const float4*)x, (const float4*)Wq, (const float4*)Wk,
        (const float4*)Wv, (const float4*)Wo,
        (__half2*)Xh, (__half2*)Wqh, (__half2*)Wkh, (__half2*)Wvh, (__half2*)Woh);

    gemm_qkv<<<dim3(48, M_ROWS / 128), 256, GEMM_SMEM>>>(Xh, Wqh, Wkh, Wvh, Qh, Kh, Vh);

    swa_attn_tc<<<dim3(NBLK, N_HEADS, BATCH), 256, AT_SMEM>>>(Qh, Kh, Vh, Ah);

    gemm_h16<<<dim3(16, M_ROWS / 128), 256, GEMM_SMEM>>>(Ah, Woh, (float*)d_out);
}